// round 10
// baseline (speedup 1.0000x reference)
#include <cuda_runtime.h>
#include <cuda_bf16.h>
#include <math.h>
#include <stdint.h>

#define T_LEN 64000
#define B_SZ  2
#define NS    3999
#define NF    3999
#define BS_TOT (B_SZ*NS)
#define HFAST 32
#define NCTA  126
#define MROWS 64
#define TILE_U4 1152            // uint4 per layer-IO tile (hi 576 + lo 576)

// smem byte offsets
#define SM_X0  0                // X buf0 [64][72] bf16 hi ; +9216 lo
#define SM_X1  18432
#define SM_H0  36864
#define SM_H1  55296
#define SM_WI  73728            // Wih^T [192][72] bf16 hi ; +27648 lo
#define SM_WH  129024
#define SM_BIAS 184320          // 256 floats
#define SM_SIW  185344          // siW[64], sib[64]
#define SM_XW   185856          // x windows [64][32] f32
#define SMEM_SZ 194048

__device__ uint4 d_lay[2][(size_t)NCTA*32*TILE_U4];
__device__ float d_W2[64*64];
__device__ float d_b2[64];
__device__ float d_A[BS_TOT*HFAST];
__device__ float d_G[BS_TOT*HFAST];
__device__ float d_S[BS_TOT*32];

typedef unsigned uu;

__device__ __forceinline__ uu s2u(const void* p){
    uu a; asm("{.reg .u64 t; cvta.to.shared.u64 t,%1; cvt.u32.u64 %0,t;}":"=r"(a):"l"(p)); return a;
}
__device__ __forceinline__ void ldsm4(uu* r, uu a){
    asm volatile("ldmatrix.sync.aligned.m8n8.x4.shared.b16 {%0,%1,%2,%3},[%4];"
        :"=r"(r[0]),"=r"(r[1]),"=r"(r[2]),"=r"(r[3]):"r"(a));
}
__device__ __forceinline__ void mma16816(float* d, const uu* a, const uu* b){
    asm volatile("mma.sync.aligned.m16n8k16.row.col.f32.bf16.bf16.f32 "
        "{%0,%1,%2,%3},{%4,%5,%6,%7},{%8,%9},{%0,%1,%2,%3};"
        :"+f"(d[0]),"+f"(d[1]),"+f"(d[2]),"+f"(d[3])
        :"r"(a[0]),"r"(a[1]),"r"(a[2]),"r"(a[3]),"r"(b[0]),"r"(b[1]));
}
__device__ __forceinline__ float frcp(float x){
    float r; asm("rcp.approx.f32 %0,%1;":"=f"(r):"f"(x)); return r;
}
__device__ __forceinline__ void splitw(float a, float b, uu& hi, uu& lo){
    __nv_bfloat16 A=__float2bfloat16(a), B=__float2bfloat16(b);
    __nv_bfloat162 H; H.x=A; H.y=B; hi=*(uu*)&H;
    __nv_bfloat162 L=__floats2bfloat162_rn(a-__bfloat162float(A), b-__bfloat162float(B));
    lo=*(uu*)&L;
}
__device__ __forceinline__ float sigm(float x){ return frcp(1.0f+__expf(fminf(-x,30.f))); }

// generate layer-0 X tile for step t directly into smem (rank-1 input)
__device__ __forceinline__ void gen_x_tile(unsigned char* smc, int xoff,
                                           const float* xw, const float* sw, int tid, int t){
    int r=tid>>2, c=tid&3;
    float xv=xw[r*32+t];
    #pragma unroll
    for(int i=0;i<8;++i){
        int k=c*16+i*2;
        float v0=fmaxf(xv*sw[k]+sw[64+k],0.f);
        float v1=fmaxf(xv*sw[k+1]+sw[64+k+1],0.f);
        uu hi,lo; splitw(v0,v1,hi,lo);
        *(uu*)(smc+xoff+r*144+k*2)=hi;
        *(uu*)(smc+xoff+9216+r*144+k*2)=lo;
    }
}

// ---- slow: mma.sync bf16 hi/lo GRU, 4 layers x 32 steps, fused prep+head -----
__global__ void __launch_bounds__(256,1) slow_kernel(
    const float* __restrict__ x,
    const float* __restrict__ siW, const float* __restrict__ sib,
    const float* __restrict__ Wih, const float* __restrict__ Whh,
    const float* __restrict__ bih, const float* __restrict__ bhh)
{
    extern __shared__ unsigned char smc[];
    const int tid=threadIdx.x, w=tid>>5, lane=tid&31;
    const int mw=w&3, uw=w>>2;
    const int r0w=mw*16, u0w=uw*32;
    const int cta=blockIdx.x;
    const uu smb=s2u(smc);
    float* bias=(float*)(smc+SM_BIAS);
    float* xw=(float*)(smc+SM_XW);
    float* sw=(float*)(smc+SM_SIW);

    const uu arow =(uu)((r0w+(lane&15))*144 + ((lane>>4)&1)*16);
    const uu brow4=(uu)((lane&7)*144 + ((lane>>3)&1)*16 + (lane>>4)*32);

    // stage x windows + siW/sib (once)
    for(int i=tid;i<2048;i+=256){
        int r=i>>5, tt=i&31;
        int g=cta*MROWS+r;
        float v=0.f;
        if(g<BS_TOT){ int b=g/NS, s=g-b*NS; v=x[b*T_LEN+s*16+tt]; }
        xw[i]=v;
    }
    if(tid<64){ sw[tid]=siW[tid]; sw[64+tid]=sib[tid]; }
    __syncthreads();

    for(int l=0;l<4;++l){
        const uint4* inb = d_lay[l&1] + (size_t)cta*32*TILE_U4;
        uu* outb = (uu*)(d_lay[(l+1)&1] + (size_t)cta*32*TILE_U4);

        // stage weights transposed [n][k] bf16 hi/lo
        for(int i=tid;i<12288;i+=256){
            int k=i/192, n=i-k*192;
            uu off=(uu)(n*144+k*2);
            float v=Wih[l*12288+i];
            __nv_bfloat16 h=__float2bfloat16(v);
            *(__nv_bfloat16*)(smc+SM_WI+off)=h;
            *(__nv_bfloat16*)(smc+SM_WI+27648+off)=__float2bfloat16(v-__bfloat162float(h));
            v=Whh[l*12288+i];
            h=__float2bfloat16(v);
            *(__nv_bfloat16*)(smc+SM_WH+off)=h;
            *(__nv_bfloat16*)(smc+SM_WH+27648+off)=__float2bfloat16(v-__bfloat162float(h));
        }
        if(tid<128)      bias[tid]=bih[l*192+tid]+bhh[l*192+tid];   // r,z combined
        else if(tid<192) bias[tid]=bih[l*192+tid];                  // xn (cols 128..191)
        else             bias[tid]=bhh[l*192+tid-64];               // hn (cols 128..191)

        // stage X(0) into buffer 0
        if(l==0){
            gen_x_tile(smc, SM_X0, xw, sw, tid, 0);
        } else {
            uint4* xs=(uint4*)(smc+SM_X0);
            for(int i=tid;i<TILE_U4;i+=256) xs[i]=inb[i];
        }
        __syncthreads();

        float hp[4][4];
        #pragma unroll
        for(int c=0;c<4;++c){ hp[c][0]=0.f;hp[c][1]=0.f;hp[c][2]=0.f;hp[c][3]=0.f; }

        #pragma unroll 1
        for(int t=0;t<32;++t){
            const int cb=t&1, nb=cb^1;
            const uu xb=smb+SM_X0+(uu)cb*18432;
            const uu hb=smb+SM_H0+(uu)cb*18432;

            float Ar[4][4],Az[4][4],Ax[4][4],Ah[4][4];
            #pragma unroll
            for(int c=0;c<4;++c)
                #pragma unroll
                for(int e=0;e<4;++e){ Ar[c][e]=0.f;Az[c][e]=0.f;Ax[c][e]=0.f;Ah[c][e]=0.f; }

            #pragma unroll
            for(int ktp=0;ktp<2;++ktp){
                uu axh0[4],axh1[4],axl0[4],axl1[4];
                uu ahh0[4],ahh1[4],ahl0[4],ahl1[4];
                ldsm4(axh0, xb+arow+(2*ktp)*32);
                ldsm4(axh1, xb+arow+(2*ktp+1)*32);
                ldsm4(axl0, xb+9216+arow+(2*ktp)*32);
                ldsm4(axl1, xb+9216+arow+(2*ktp+1)*32);
                if(t){
                    ldsm4(ahh0, hb+arow+(2*ktp)*32);
                    ldsm4(ahh1, hb+arow+(2*ktp+1)*32);
                    ldsm4(ahl0, hb+9216+arow+(2*ktp)*32);
                    ldsm4(ahl1, hb+9216+arow+(2*ktp+1)*32);
                }
                #pragma unroll
                for(int ct=0;ct<4;++ct){
                    const uu nR=(uu)((u0w+ct*8)*144);
                    const uu nZ=nR+9216u;
                    const uu nN=nR+18432u;
                    uu bh[4],bl[4];
                    // r gate: Wih
                    ldsm4(bh, smb+SM_WI+nR+brow4+ktp*64);
                    ldsm4(bl, smb+SM_WI+27648+nR+brow4+ktp*64);
                    mma16816(Ar[ct],axh0,bh);   mma16816(Ar[ct],axh1,bh+2);
                    mma16816(Ar[ct],axh0,bl);   mma16816(Ar[ct],axh1,bl+2);
                    mma16816(Ar[ct],axl0,bh);   mma16816(Ar[ct],axl1,bh+2);
                    if(t){  // r gate: Whh
                        ldsm4(bh, smb+SM_WH+nR+brow4+ktp*64);
                        ldsm4(bl, smb+SM_WH+27648+nR+brow4+ktp*64);
                        mma16816(Ar[ct],ahh0,bh);  mma16816(Ar[ct],ahh1,bh+2);
                        mma16816(Ar[ct],ahh0,bl);  mma16816(Ar[ct],ahh1,bl+2);
                        mma16816(Ar[ct],ahl0,bh);  mma16816(Ar[ct],ahl1,bh+2);
                    }
                    // z gate: Wih
                    ldsm4(bh, smb+SM_WI+nZ+brow4+ktp*64);
                    ldsm4(bl, smb+SM_WI+27648+nZ+brow4+ktp*64);
                    mma16816(Az[ct],axh0,bh);   mma16816(Az[ct],axh1,bh+2);
                    mma16816(Az[ct],axh0,bl);   mma16816(Az[ct],axh1,bl+2);
                    mma16816(Az[ct],axl0,bh);   mma16816(Az[ct],axl1,bh+2);
                    if(t){  // z gate: Whh
                        ldsm4(bh, smb+SM_WH+nZ+brow4+ktp*64);
                        ldsm4(bl, smb+SM_WH+27648+nZ+brow4+ktp*64);
                        mma16816(Az[ct],ahh0,bh);  mma16816(Az[ct],ahh1,bh+2);
                        mma16816(Az[ct],ahh0,bl);  mma16816(Az[ct],ahh1,bl+2);
                        mma16816(Az[ct],ahl0,bh);  mma16816(Az[ct],ahl1,bh+2);
                    }
                    // xn: Wih only
                    ldsm4(bh, smb+SM_WI+nN+brow4+ktp*64);
                    ldsm4(bl, smb+SM_WI+27648+nN+brow4+ktp*64);
                    mma16816(Ax[ct],axh0,bh);   mma16816(Ax[ct],axh1,bh+2);
                    mma16816(Ax[ct],axh0,bl);   mma16816(Ax[ct],axh1,bl+2);
                    mma16816(Ax[ct],axl0,bh);   mma16816(Ax[ct],axl1,bh+2);
                    // hn: Whh only
                    if(t){
                        ldsm4(bh, smb+SM_WH+nN+brow4+ktp*64);
                        ldsm4(bl, smb+SM_WH+27648+nN+brow4+ktp*64);
                        mma16816(Ah[ct],ahh0,bh);  mma16816(Ah[ct],ahh1,bh+2);
                        mma16816(Ah[ct],ahh0,bl);  mma16816(Ah[ct],ahh1,bl+2);
                        mma16816(Ah[ct],ahl0,bh);  mma16816(Ah[ct],ahl1,bh+2);
                    }
                }
            }

            // prefetch next X tile (gmem) for l>0
            uint4 pf[5];
            if(l>0 && t<31){
                const uint4* nx=inb+(size_t)(t+1)*TILE_U4;
                #pragma unroll
                for(int j=0;j<5;++j){ int idx=tid+j*256; if(idx<TILE_U4) pf[j]=nx[idx]; }
            }

            // gates in registers (m16n8k16 D layout)
            float hv[4][4];
            #pragma unroll
            for(int ct=0;ct<4;++ct){
                const int ue=u0w+ct*8+(lane&3)*2;
                #pragma unroll
                for(int e=0;e<4;++e){
                    const int u=ue+(e&1);
                    float ar=Ar[ct][e]+bias[u];
                    float az=Az[ct][e]+bias[64+u];
                    float ax=Ax[ct][e]+bias[128+u];
                    float ah=Ah[ct][e]+bias[192+u];
                    float tr=__expf(fminf(-ar,30.f));
                    float tz=__expf(fminf(-az,30.f));
                    float q=frcp((1.f+tr)*(1.f+tz));
                    float r=q*(1.f+tz), z=q*(1.f+tr);
                    float wv=ax+r*ah;
                    float tn=__expf(fminf(-2.f*wv,30.f));
                    float n=2.f*frcp(1.f+tn)-1.f;
                    float hn=z*(hp[ct][e]-n)+n;
                    hp[ct][e]=hn; hv[ct][e]=hn;
                }
            }

            // write H(t) -> alternate buffer; out tile (bf16 relu) for l<3
            const uu hn_off=(uu)(SM_H0+nb*18432);
            const bool wout=(l<3);
            uu* oti=outb+(size_t)t*4608;
            #pragma unroll
            for(int ct=0;ct<4;++ct){
                const int ue=u0w+ct*8+(lane&3)*2;
                const int rA=r0w+(lane>>2);
                uu hi,lo;
                splitw(hv[ct][0],hv[ct][1],hi,lo);
                *(uu*)(smc+hn_off+rA*144+ue*2)=hi;
                *(uu*)(smc+hn_off+9216+rA*144+ue*2)=lo;
                splitw(hv[ct][2],hv[ct][3],hi,lo);
                *(uu*)(smc+hn_off+(rA+8)*144+ue*2)=hi;
                *(uu*)(smc+hn_off+9216+(rA+8)*144+ue*2)=lo;
                if(wout){
                    uu rhi,rlo;
                    splitw(fmaxf(hv[ct][0],0.f),fmaxf(hv[ct][1],0.f),rhi,rlo);
                    oti[rA*36+(ue>>1)]=rhi;
                    oti[2304+rA*36+(ue>>1)]=rlo;
                    splitw(fmaxf(hv[ct][2],0.f),fmaxf(hv[ct][3],0.f),rhi,rlo);
                    oti[(rA+8)*36+(ue>>1)]=rhi;
                    oti[2304+(rA+8)*36+(ue>>1)]=rlo;
                }
            }

            // next X tile -> alternate buffer
            if(t<31){
                const int xn_off=SM_X0+nb*18432;
                if(l==0){
                    gen_x_tile(smc, xn_off, xw, sw, tid, t+1);
                } else {
                    uint4* xs=(uint4*)(smc+xn_off);
                    #pragma unroll
                    for(int j=0;j<5;++j){ int idx=tid+j*256; if(idx<TILE_U4) xs[idx]=pf[j]; }
                }
            }
            __syncthreads();   // single barrier: all writes visible for step t+1
        }
    }

    // ---- fused head: eps = relu(h31) @ W2 + b2 -> d_A, d_G -------------------
    // h31 (pre-relu, bf16 hi/lo) sits in H buffer 0 (t=31 wrote nb=0).
    float* w2s=(float*)smc;                    // reuse X0 region (16 KB)
    float* b2s=(float*)(smc+16384);
    float* hr =(float*)(smc+SM_X1);            // 64x65 f32 in X1 region
    for(int i=tid;i<4096;i+=256) w2s[i]=d_W2[i];
    if(tid<64) b2s[tid]=d_b2[tid];
    for(int i=tid;i<4096;i+=256){
        int m=i>>6, k=i&63;
        float v=__bfloat162float(*(const __nv_bfloat16*)(smc+SM_H0+m*144+k*2))
               +__bfloat162float(*(const __nv_bfloat16*)(smc+SM_H0+9216+m*144+k*2));
        hr[m*65+k]=fmaxf(v,0.f);
    }
    __syncthreads();
    for(int i=tid;i<4096;i+=256){
        int m=i>>6, u=i&63;
        float a=b2s[u];
        #pragma unroll 8
        for(int k=0;k<64;++k) a+=hr[m*65+k]*w2s[k*64+u];
        int g=cta*MROWS+m;
        if(g<BS_TOT){
            if(u<HFAST) d_A[g*HFAST+u]=sigm(a);
            else        d_G[g*HFAST+u-HFAST]=a;
        }
    }
}

// ---- fuse: W2 = soW @ s2sW, b2 = sob @ s2sW + s2sb ----------------------------
__global__ void fuse_kernel(const float* __restrict__ soW, const float* __restrict__ sob,
                            const float* __restrict__ s2sW, const float* __restrict__ s2sb)
{
    int tid=threadIdx.x;
    for(int i=tid;i<4096;i+=256){
        int k=i>>6, v=i&63;
        float a=0.f;
        for(int u=0;u<64;++u) a+=soW[k*64+u]*s2sW[u*64+v];
        d_W2[i]=a;
    }
    if(tid<64){
        float a=s2sb[tid];
        for(int u=0;u<64;++u) a+=sob[u]*s2sW[u*64+tid];
        d_b2[tid]=a;
    }
}

// ---- fast path + overlap-add (verified) ----------------------------------------
__global__ void __launch_bounds__(256) fast_kernel(
    const float* __restrict__ x, const float* __restrict__ finW,
    const float* __restrict__ finb, const float* __restrict__ foutW,
    const float* __restrict__ foutb)
{
    int w=(blockIdx.x*blockDim.x+threadIdx.x)>>5;
    int h=threadIdx.x&31;
    if(w>=BS_TOT) return;
    int b=w/NF, f=w-b*NF;
    float A=d_A[w*HFAST+h], G=d_G[w*HFAST+h];
    float fw=__ldg(&finW[h]), fb=__ldg(&finb[h]);
    float fo=__ldg(&foutW[h]), fob=__ldg(&foutb[0]);
    const float* xp=x+b*T_LEN+f*16;
    float hsv=0.f;
    #pragma unroll
    for(int t=0;t<32;++t){
        float e=(xp[t]*fw+fb)*G;
        hsv=A*hsv+e;
        float y=hsv*fo;
        #pragma unroll
        for(int mm=16;mm;mm>>=1) y+=__shfl_xor_sync(0xffffffffu,y,mm);
        if(h==t) d_S[w*32+t]=y+fob;
    }
}
__global__ void __launch_bounds__(256) oadd_kernel(float* __restrict__ out)
{
    int idx=blockIdx.x*blockDim.x+threadIdx.x;
    if(idx>=B_SZ*T_LEN) return;
    int b=idx/T_LEN, i=idx-b*T_LEN;
    int f1=i>>4, j=i&15;
    float v=0.f;
    if(f1<NF) v+=d_S[(b*NF+f1)*32+j];
    if(f1>=1) v+=d_S[(b*NF+f1-1)*32+j+16];
    out[idx]=v;
}

extern "C" void kernel_launch(void* const* d_in, const int* in_sizes, int n_in,
                              void* d_out, int out_size)
{
    const float* x    =(const float*)d_in[0];
    const float* siW  =(const float*)d_in[1];
    const float* sib  =(const float*)d_in[2];
    const float* Wih  =(const float*)d_in[3];
    const float* Whh  =(const float*)d_in[4];
    const float* bih  =(const float*)d_in[5];
    const float* bhh  =(const float*)d_in[6];
    const float* soW  =(const float*)d_in[7];
    const float* sob  =(const float*)d_in[8];
    const float* s2sW =(const float*)d_in[9];
    const float* s2sb =(const float*)d_in[10];
    const float* finW =(const float*)d_in[11];
    const float* finb =(const float*)d_in[12];
    const float* foW  =(const float*)d_in[13];
    const float* fob  =(const float*)d_in[14];
    float* out=(float*)d_out;

    cudaFuncSetAttribute(slow_kernel, cudaFuncAttributeMaxDynamicSharedMemorySize, SMEM_SZ);
    fuse_kernel<<<1,256>>>(soW,sob,s2sW,s2sb);
    slow_kernel<<<NCTA,256,SMEM_SZ>>>(x,siW,sib,Wih,Whh,bih,bhh);
    fast_kernel<<<(BS_TOT*32+255)/256,256>>>(x,finW,finb,foW,fob);
    oadd_kernel<<<(B_SZ*T_LEN+255)/256,256>>>(out);
}

// round 11
// speedup vs baseline: 1.2660x; 1.2660x over previous
#include <cuda_runtime.h>
#include <cuda_bf16.h>
#include <math.h>
#include <stdint.h>

#define T_LEN 64000
#define B_SZ  2
#define NS    3999
#define NF    3999
#define BS_TOT (B_SZ*NS)
#define HFAST 32
#define NCTA  126
#define MROWS 64
#define TILE_U4 1152            // uint4 per layer-IO tile (hi 576 + lo 576)

// smem byte offsets
#define SM_X   0                // X [64][72] bf16 hi ; +9216 lo
#define SM_H   18432            // H [64][72] bf16 hi ; +9216 lo
#define SM_WI  36864            // Wih^T [192][72] bf16 hi ; +27648 lo
#define SM_WH  92160            // Whh^T same
#define SM_BIAS 147456          // 256 floats
#define SM_XW   148480          // x windows [64][32] f32
#define SM_SIW  156672          // siW[64], sib[64]
#define SMEM_SZ 157184

__device__ uint4 d_lay[2][(size_t)NCTA*32*TILE_U4];
__device__ float d_W2[64*64];
__device__ float d_b2[64];
__device__ float d_A[BS_TOT*HFAST];
__device__ float d_G[BS_TOT*HFAST];
__device__ float d_S[BS_TOT*32];

typedef unsigned uu;

__device__ __forceinline__ uu s2u(const void* p){
    uu a; asm("{.reg .u64 t; cvta.to.shared.u64 t,%1; cvt.u32.u64 %0,t;}":"=r"(a):"l"(p)); return a;
}
__device__ __forceinline__ void ldsm4(uu* r, uu a){
    asm volatile("ldmatrix.sync.aligned.m8n8.x4.shared.b16 {%0,%1,%2,%3},[%4];"
        :"=r"(r[0]),"=r"(r[1]),"=r"(r[2]),"=r"(r[3]):"r"(a));
}
__device__ __forceinline__ void ldsm2(uu* r, uu a){
    asm volatile("ldmatrix.sync.aligned.m8n8.x2.shared.b16 {%0,%1},[%2];"
        :"=r"(r[0]),"=r"(r[1]):"r"(a));
}
__device__ __forceinline__ void mma16816(float* d, const uu* a, const uu* b){
    asm volatile("mma.sync.aligned.m16n8k16.row.col.f32.bf16.bf16.f32 "
        "{%0,%1,%2,%3},{%4,%5,%6,%7},{%8,%9},{%0,%1,%2,%3};"
        :"+f"(d[0]),"+f"(d[1]),"+f"(d[2]),"+f"(d[3])
        :"r"(a[0]),"r"(a[1]),"r"(a[2]),"r"(a[3]),"r"(b[0]),"r"(b[1]));
}
__device__ __forceinline__ float frcp(float x){
    float r; asm("rcp.approx.f32 %0,%1;":"=f"(r):"f"(x)); return r;
}
__device__ __forceinline__ void splitw(float a, float b, uu& hi, uu& lo){
    __nv_bfloat16 A=__float2bfloat16(a), B=__float2bfloat16(b);
    __nv_bfloat162 H; H.x=A; H.y=B; hi=*(uu*)&H;
    __nv_bfloat162 L=__floats2bfloat162_rn(a-__bfloat162float(A), b-__bfloat162float(B));
    lo=*(uu*)&L;
}
__device__ __forceinline__ float sigm(float x){ return frcp(1.0f+__expf(fminf(-x,30.f))); }

// ---- slow: mma.sync bf16 hi/lo GRU, 4 layers x 32 steps, fused prep+head -----
__global__ void __launch_bounds__(256,1) slow_kernel(
    const float* __restrict__ x,
    const float* __restrict__ siW, const float* __restrict__ sib,
    const float* __restrict__ Wih, const float* __restrict__ Whh,
    const float* __restrict__ bih, const float* __restrict__ bhh)
{
    extern __shared__ unsigned char smc[];
    const int tid=threadIdx.x, w=tid>>5, lane=tid&31;
    const int mw=w&3, uw=w>>2;
    const int r0w=mw*16, u0w=uw*32;
    const int cta=blockIdx.x;
    const uu smb=s2u(smc);
    float* bias=(float*)(smc+SM_BIAS);
    float* xw=(float*)(smc+SM_XW);
    float* sw=(float*)(smc+SM_SIW);

    // ldmatrix address components (identical to the 715us kernel)
    const uu arow=(uu)((r0w+(lane&15))*144 + ((lane>>4)&1)*16);   // A: X/H tiles
    const uu brow=(uu)((lane&7)*144 + ((lane>>3)&1)*16);          // B: W tiles

    // stage x windows + siW/sib (once per CTA)
    for(int i=tid;i<2048;i+=256){
        int r=i>>5, tt=i&31;
        int g=cta*MROWS+r;
        float v=0.f;
        if(g<BS_TOT){ int b=g/NS, s=g-b*NS; v=x[b*T_LEN+s*16+tt]; }
        xw[i]=v;
    }
    if(tid<64){ sw[tid]=siW[tid]; sw[64+tid]=sib[tid]; }
    __syncthreads();

    const int gr=tid>>2, gc=tid&3;   // layer-0 generator assignment

    for(int l=0;l<4;++l){
        const uint4* inb = d_lay[l&1] + (size_t)cta*32*TILE_U4;
        uu* outb = (uu*)(d_lay[(l+1)&1] + (size_t)cta*32*TILE_U4);

        // stage weights transposed [n][k] bf16 hi/lo
        for(int i=tid;i<12288;i+=256){
            int k=i/192, n=i-k*192;
            uu off=(uu)(n*144+k*2);
            float v=Wih[l*12288+i];
            __nv_bfloat16 h=__float2bfloat16(v);
            *(__nv_bfloat16*)(smc+SM_WI+off)=h;
            *(__nv_bfloat16*)(smc+SM_WI+27648+off)=__float2bfloat16(v-__bfloat162float(h));
            v=Whh[l*12288+i];
            h=__float2bfloat16(v);
            *(__nv_bfloat16*)(smc+SM_WH+off)=h;
            *(__nv_bfloat16*)(smc+SM_WH+27648+off)=__float2bfloat16(v-__bfloat162float(h));
        }
        if(tid<128)      bias[tid]=bih[l*192+tid]+bhh[l*192+tid];   // r,z combined
        else if(tid<192) bias[tid]=bih[l*192+tid];                  // xn (cols 128..191)
        else             bias[tid]=bhh[l*192+tid-64];               // hn (cols 128..191)

        // stage X(0)
        if(l==0){
            float xv=xw[gr*32+0];
            #pragma unroll
            for(int i=0;i<8;++i){
                int k=gc*16+i*2;
                float v0=fmaxf(xv*sw[k]+sw[64+k],0.f);
                float v1=fmaxf(xv*sw[k+1]+sw[64+k+1],0.f);
                uu hi,lo; splitw(v0,v1,hi,lo);
                *(uu*)(smc+SM_X+gr*144+k*2)=hi;
                *(uu*)(smc+SM_X+9216+gr*144+k*2)=lo;
            }
        } else {
            uint4* xs=(uint4*)(smc+SM_X);
            for(int i=tid;i<TILE_U4;i+=256) xs[i]=inb[i];
        }
        __syncthreads();

        float hp[4][4];
        #pragma unroll
        for(int c=0;c<4;++c){ hp[c][0]=0.f;hp[c][1]=0.f;hp[c][2]=0.f;hp[c][3]=0.f; }

        #pragma unroll 1
        for(int t=0;t<32;++t){
            float Ar[4][4],Az[4][4],Ax[4][4],Ah[4][4];
            #pragma unroll
            for(int c=0;c<4;++c)
                #pragma unroll
                for(int e=0;e<4;++e){ Ar[c][e]=0.f;Az[c][e]=0.f;Ax[c][e]=0.f;Ah[c][e]=0.f; }

            #pragma unroll
            for(int kt=0;kt<4;++kt){
                uu axh[4],axl[4],ahh[4],ahl[4];
                ldsm4(axh, smb+SM_X+arow+kt*32);
                ldsm4(axl, smb+SM_X+9216+arow+kt*32);
                if(t){
                    ldsm4(ahh, smb+SM_H+arow+kt*32);
                    ldsm4(ahl, smb+SM_H+9216+arow+kt*32);
                }
                #pragma unroll
                for(int ct=0;ct<4;++ct){
                    const uu nR=(uu)((u0w+ct*8)*144);
                    const uu nZ=nR+(uu)(64*144);
                    const uu nN=nR+(uu)(128*144);
                    uu b0[2],b1[2];
                    // r gate: X@Wih_r (+ H@Whh_r)
                    ldsm2(b0, smb+SM_WI+nR+brow+kt*32);
                    ldsm2(b1, smb+SM_WI+27648+nR+brow+kt*32);
                    mma16816(Ar[ct],axh,b0); mma16816(Ar[ct],axh,b1); mma16816(Ar[ct],axl,b0);
                    if(t){
                        ldsm2(b0, smb+SM_WH+nR+brow+kt*32);
                        ldsm2(b1, smb+SM_WH+27648+nR+brow+kt*32);
                        mma16816(Ar[ct],ahh,b0); mma16816(Ar[ct],ahh,b1); mma16816(Ar[ct],ahl,b0);
                    }
                    // z gate
                    ldsm2(b0, smb+SM_WI+nZ+brow+kt*32);
                    ldsm2(b1, smb+SM_WI+27648+nZ+brow+kt*32);
                    mma16816(Az[ct],axh,b0); mma16816(Az[ct],axh,b1); mma16816(Az[ct],axl,b0);
                    if(t){
                        ldsm2(b0, smb+SM_WH+nZ+brow+kt*32);
                        ldsm2(b1, smb+SM_WH+27648+nZ+brow+kt*32);
                        mma16816(Az[ct],ahh,b0); mma16816(Az[ct],ahh,b1); mma16816(Az[ct],ahl,b0);
                    }
                    // xn (Wih only)
                    ldsm2(b0, smb+SM_WI+nN+brow+kt*32);
                    ldsm2(b1, smb+SM_WI+27648+nN+brow+kt*32);
                    mma16816(Ax[ct],axh,b0); mma16816(Ax[ct],axh,b1); mma16816(Ax[ct],axl,b0);
                    // hn (Whh only)
                    if(t){
                        ldsm2(b0, smb+SM_WH+nN+brow+kt*32);
                        ldsm2(b1, smb+SM_WH+27648+nN+brow+kt*32);
                        mma16816(Ah[ct],ahh,b0); mma16816(Ah[ct],ahh,b1); mma16816(Ah[ct],ahl,b0);
                    }
                }
            }

            // prefetch / generate next X tile
            uint4 pf[5];
            uu gh[8], gl[8];
            if(t<31){
                if(l==0){
                    float xv=xw[gr*32+t+1];
                    #pragma unroll
                    for(int i=0;i<8;++i){
                        int k=gc*16+i*2;
                        float v0=fmaxf(xv*sw[k]+sw[64+k],0.f);
                        float v1=fmaxf(xv*sw[k+1]+sw[64+k+1],0.f);
                        splitw(v0,v1,gh[i],gl[i]);
                    }
                } else {
                    const uint4* nx=inb+(size_t)(t+1)*TILE_U4;
                    #pragma unroll
                    for(int j=0;j<5;++j){ int idx=tid+j*256; if(idx<TILE_U4) pf[j]=nx[idx]; }
                }
            }

            // gates: fully in registers (m16n8k16 D layout)
            float hv[4][4];
            #pragma unroll
            for(int ct=0;ct<4;++ct){
                const int ue=u0w+ct*8+(lane&3)*2;
                #pragma unroll
                for(int e=0;e<4;++e){
                    const int u=ue+(e&1);
                    float ar=Ar[ct][e]+bias[u];
                    float az=Az[ct][e]+bias[64+u];
                    float ax=Ax[ct][e]+bias[128+u];
                    float ah=Ah[ct][e]+bias[192+u];
                    float tr=__expf(fminf(-ar,30.f));
                    float tz=__expf(fminf(-az,30.f));
                    float q=frcp((1.f+tr)*(1.f+tz));
                    float r=q*(1.f+tz), z=q*(1.f+tr);
                    float wv=ax+r*ah;
                    float tn=__expf(fminf(-2.f*wv,30.f));
                    float n=2.f*frcp(1.f+tn)-1.f;
                    float hn=z*(hp[ct][e]-n)+n;
                    hp[ct][e]=hn; hv[ct][e]=hn;
                }
            }

            __syncthreads();   // S1: all smem reads of step t complete

            const bool wout=(l<3);
            uu* oti=outb+(size_t)t*4608;
            #pragma unroll
            for(int ct=0;ct<4;++ct){
                const int ue=u0w+ct*8+(lane&3)*2;
                const int rA=r0w+(lane>>2);
                uu hi,lo;
                splitw(hv[ct][0],hv[ct][1],hi,lo);
                *(uu*)(smc+SM_H+rA*144+ue*2)=hi;
                *(uu*)(smc+SM_H+9216+rA*144+ue*2)=lo;
                splitw(hv[ct][2],hv[ct][3],hi,lo);
                *(uu*)(smc+SM_H+(rA+8)*144+ue*2)=hi;
                *(uu*)(smc+SM_H+9216+(rA+8)*144+ue*2)=lo;
                if(wout){
                    uu rhi,rlo;
                    splitw(fmaxf(hv[ct][0],0.f),fmaxf(hv[ct][1],0.f),rhi,rlo);
                    oti[rA*36+(ue>>1)]=rhi;
                    oti[2304+rA*36+(ue>>1)]=rlo;
                    splitw(fmaxf(hv[ct][2],0.f),fmaxf(hv[ct][3],0.f),rhi,rlo);
                    oti[(rA+8)*36+(ue>>1)]=rhi;
                    oti[2304+(rA+8)*36+(ue>>1)]=rlo;
                }
            }
            if(t<31){
                if(l==0){
                    #pragma unroll
                    for(int i=0;i<8;++i){
                        int k=gc*16+i*2;
                        *(uu*)(smc+SM_X+gr*144+k*2)=gh[i];
                        *(uu*)(smc+SM_X+9216+gr*144+k*2)=gl[i];
                    }
                } else {
                    uint4* xs=(uint4*)(smc+SM_X);
                    #pragma unroll
                    for(int j=0;j<5;++j){ int idx=tid+j*256; if(idx<TILE_U4) xs[idx]=pf[j]; }
                }
            }
            __syncthreads();   // S2: writes visible for step t+1
        }
    }

    // ---- fused head: eps = relu(h31) @ W2 + b2 -> d_A, d_G -------------------
    // h31 (pre-relu bf16 hi/lo) is in SM_H.
    float* w2s=(float*)smc;                 // reuse X region (16 KB)
    float* b2s=(float*)(smc+16384);
    float* hr =(float*)(smc+SM_WI);         // 64x65 f32 in WI region
    for(int i=tid;i<4096;i+=256) w2s[i]=d_W2[i];
    if(tid<64) b2s[tid]=d_b2[tid];
    for(int i=tid;i<4096;i+=256){
        int m=i>>6, k=i&63;
        float v=__bfloat162float(*(const __nv_bfloat16*)(smc+SM_H+m*144+k*2))
               +__bfloat162float(*(const __nv_bfloat16*)(smc+SM_H+9216+m*144+k*2));
        hr[m*65+k]=fmaxf(v,0.f);
    }
    __syncthreads();
    for(int i=tid;i<4096;i+=256){
        int m=i>>6, u=i&63;
        float a=b2s[u];
        #pragma unroll 8
        for(int k=0;k<64;++k) a+=hr[m*65+k]*w2s[k*64+u];
        int g=cta*MROWS+m;
        if(g<BS_TOT){
            if(u<HFAST) d_A[g*HFAST+u]=sigm(a);
            else        d_G[g*HFAST+u-HFAST]=a;
        }
    }
}

// ---- fuse: W2 = soW @ s2sW, b2 = sob @ s2sW + s2sb ----------------------------
__global__ void fuse_kernel(const float* __restrict__ soW, const float* __restrict__ sob,
                            const float* __restrict__ s2sW, const float* __restrict__ s2sb)
{
    int tid=threadIdx.x;
    for(int i=tid;i<4096;i+=256){
        int k=i>>6, v=i&63;
        float a=0.f;
        for(int u=0;u<64;++u) a+=soW[k*64+u]*s2sW[u*64+v];
        d_W2[i]=a;
    }
    if(tid<64){
        float a=s2sb[tid];
        for(int u=0;u<64;++u) a+=sob[u]*s2sW[u*64+tid];
        d_b2[tid]=a;
    }
}

// ---- fast path + overlap-add (verified) ----------------------------------------
__global__ void __launch_bounds__(256) fast_kernel(
    const float* __restrict__ x, const float* __restrict__ finW,
    const float* __restrict__ finb, const float* __restrict__ foutW,
    const float* __restrict__ foutb)
{
    int w=(blockIdx.x*blockDim.x+threadIdx.x)>>5;
    int h=threadIdx.x&31;
    if(w>=BS_TOT) return;
    int b=w/NF, f=w-b*NF;
    float A=d_A[w*HFAST+h], G=d_G[w*HFAST+h];
    float fw=__ldg(&finW[h]), fb=__ldg(&finb[h]);
    float fo=__ldg(&foutW[h]), fob=__ldg(&foutb[0]);
    const float* xp=x+b*T_LEN+f*16;
    float hsv=0.f;
    #pragma unroll
    for(int t=0;t<32;++t){
        float e=(xp[t]*fw+fb)*G;
        hsv=A*hsv+e;
        float y=hsv*fo;
        #pragma unroll
        for(int mm=16;mm;mm>>=1) y+=__shfl_xor_sync(0xffffffffu,y,mm);
        if(h==t) d_S[w*32+t]=y+fob;
    }
}
__global__ void __launch_bounds__(256) oadd_kernel(float* __restrict__ out)
{
    int idx=blockIdx.x*blockDim.x+threadIdx.x;
    if(idx>=B_SZ*T_LEN) return;
    int b=idx/T_LEN, i=idx-b*T_LEN;
    int f1=i>>4, j=i&15;
    float v=0.f;
    if(f1<NF) v+=d_S[(b*NF+f1)*32+j];
    if(f1>=1) v+=d_S[(b*NF+f1-1)*32+j+16];
    out[idx]=v;
}

extern "C" void kernel_launch(void* const* d_in, const int* in_sizes, int n_in,
                              void* d_out, int out_size)
{
    const float* x    =(const float*)d_in[0];
    const float* siW  =(const float*)d_in[1];
    const float* sib  =(const float*)d_in[2];
    const float* Wih  =(const float*)d_in[3];
    const float* Whh  =(const float*)d_in[4];
    const float* bih  =(const float*)d_in[5];
    const float* bhh  =(const float*)d_in[6];
    const float* soW  =(const float*)d_in[7];
    const float* sob  =(const float*)d_in[8];
    const float* s2sW =(const float*)d_in[9];
    const float* s2sb =(const float*)d_in[10];
    const float* finW =(const float*)d_in[11];
    const float* finb =(const float*)d_in[12];
    const float* foW  =(const float*)d_in[13];
    const float* fob  =(const float*)d_in[14];
    float* out=(float*)d_out;

    cudaFuncSetAttribute(slow_kernel, cudaFuncAttributeMaxDynamicSharedMemorySize, SMEM_SZ);
    fuse_kernel<<<1,256>>>(soW,sob,s2sW,s2sb);
    slow_kernel<<<NCTA,256,SMEM_SZ>>>(x,siW,sib,Wih,Whh,bih,bhh);
    fast_kernel<<<(BS_TOT*32+255)/256,256>>>(x,finW,finb,foW,fob);
    oadd_kernel<<<(B_SZ*T_LEN+255)/256,256>>>(out);
}

// round 13
// speedup vs baseline: 1.6019x; 1.2653x over previous
#include <cuda_runtime.h>
#include <cuda_fp16.h>
#include <math.h>
#include <stdint.h>

#define T_LEN 64000
#define B_SZ  2
#define NS    3999
#define NF    3999
#define BS_TOT (B_SZ*NS)
#define HFAST 32
#define NCTA  126
#define MROWS 64
#define TILE_U4 576             // uint4 per layer-IO tile (fp16 [64][72])

// smem byte offsets
#define SM_X   0                // X [64][72] fp16
#define SM_H   9216             // H [64][72] fp16
#define SM_WI  18432            // Wih^T [192][72] fp16 hi ; +27648 lo
#define SM_WH  73728            // Whh^T same
#define SM_BIAS 129024          // 256 floats
#define SM_XW   130048          // x windows [64][32] f32
#define SM_SIW  138240          // siW[64], sib[64]
#define SMEM_SZ 138752

__device__ uint4 d_lay[2][(size_t)NCTA*32*TILE_U4];
__device__ float d_W2[64*64];
__device__ float d_b2[64];
__device__ float d_A[BS_TOT*HFAST];
__device__ float d_G[BS_TOT*HFAST];
__device__ float d_S[BS_TOT*32];

typedef unsigned uu;

__device__ __forceinline__ uu s2u(const void* p){
    uu a; asm("{.reg .u64 t; cvta.to.shared.u64 t,%1; cvt.u32.u64 %0,t;}":"=r"(a):"l"(p)); return a;
}
__device__ __forceinline__ void ldsm4(uu* r, uu a){
    asm volatile("ldmatrix.sync.aligned.m8n8.x4.shared.b16 {%0,%1,%2,%3},[%4];"
        :"=r"(r[0]),"=r"(r[1]),"=r"(r[2]),"=r"(r[3]):"r"(a));
}
__device__ __forceinline__ void ldsm2(uu* r, uu a){
    asm volatile("ldmatrix.sync.aligned.m8n8.x2.shared.b16 {%0,%1},[%2];"
        :"=r"(r[0]),"=r"(r[1]):"r"(a));
}
__device__ __forceinline__ void mma16816(float* d, const uu* a, const uu* b){
    asm volatile("mma.sync.aligned.m16n8k16.row.col.f32.f16.f16.f32 "
        "{%0,%1,%2,%3},{%4,%5,%6,%7},{%8,%9},{%0,%1,%2,%3};"
        :"+f"(d[0]),"+f"(d[1]),"+f"(d[2]),"+f"(d[3])
        :"r"(a[0]),"r"(a[1]),"r"(a[2]),"r"(a[3]),"r"(b[0]),"r"(b[1]));
}
__device__ __forceinline__ float frcp(float x){
    float r; asm("rcp.approx.f32 %0,%1;":"=f"(r):"f"(x)); return r;
}
__device__ __forceinline__ uu pack2h(float a, float b){
    __half2 h=__floats2half2_rn(a,b); return *(uu*)&h;
}
__device__ __forceinline__ float sigm(float x){ return frcp(1.0f+__expf(fminf(-x,30.f))); }

// ---- slow: mma.sync fp16 (weights hi/lo) GRU, fused prep+head ----------------
__global__ void __launch_bounds__(256,1) slow_kernel(
    const float* __restrict__ x,
    const float* __restrict__ siW, const float* __restrict__ sib,
    const float* __restrict__ Wih, const float* __restrict__ Whh,
    const float* __restrict__ bih, const float* __restrict__ bhh)
{
    extern __shared__ unsigned char smc[];
    const int tid=threadIdx.x, w=tid>>5, lane=tid&31;
    const int mw=w&3, uw=w>>2;
    const int r0w=mw*16, u0w=uw*32;
    const int cta=blockIdx.x;
    const uu smb=s2u(smc);
    float* bias=(float*)(smc+SM_BIAS);
    float* xw=(float*)(smc+SM_XW);
    float* sw=(float*)(smc+SM_SIW);

    const uu arow=(uu)((r0w+(lane&15))*144 + ((lane>>4)&1)*16);   // A: X/H tiles
    const uu brow=(uu)((lane&7)*144 + ((lane>>3)&1)*16);          // B: W tiles

    // stage x windows + siW/sib (once per CTA)
    for(int i=tid;i<2048;i+=256){
        int r=i>>5, tt=i&31;
        int g=cta*MROWS+r;
        float v=0.f;
        if(g<BS_TOT){ int b=g/NS, s=g-b*NS; v=x[b*T_LEN+s*16+tt]; }
        xw[i]=v;
    }
    if(tid<64){ sw[tid]=siW[tid]; sw[64+tid]=sib[tid]; }
    __syncthreads();

    const int gr=tid>>2, gc=tid&3;   // layer-0 generator assignment

    for(int l=0;l<4;++l){
        const uint4* inb = d_lay[l&1] + (size_t)cta*32*TILE_U4;
        uu* outb = (uu*)(d_lay[(l+1)&1] + (size_t)cta*32*TILE_U4);

        // stage weights transposed [n][k] fp16 hi/lo
        for(int i=tid;i<12288;i+=256){
            int k=i/192, n=i-k*192;
            uu off=(uu)(n*144+k*2);
            float v=Wih[l*12288+i];
            __half h=__float2half_rn(v);
            *(__half*)(smc+SM_WI+off)=h;
            *(__half*)(smc+SM_WI+27648+off)=__float2half_rn(v-__half2float(h));
            v=Whh[l*12288+i];
            h=__float2half_rn(v);
            *(__half*)(smc+SM_WH+off)=h;
            *(__half*)(smc+SM_WH+27648+off)=__float2half_rn(v-__half2float(h));
        }
        if(tid<128)      bias[tid]=bih[l*192+tid]+bhh[l*192+tid];   // r,z combined
        else if(tid<192) bias[tid]=bih[l*192+tid];                  // xn (cols 128..191)
        else             bias[tid]=bhh[l*192+tid-64];               // hn (cols 128..191)

        // stage X(0)
        if(l==0){
            float xv=xw[gr*32+0];
            #pragma unroll
            for(int i=0;i<8;++i){
                int k=gc*16+i*2;
                float v0=fmaxf(xv*sw[k]+sw[64+k],0.f);
                float v1=fmaxf(xv*sw[k+1]+sw[64+k+1],0.f);
                *(uu*)(smc+SM_X+gr*144+k*2)=pack2h(v0,v1);
            }
        } else {
            uint4* xs=(uint4*)(smc+SM_X);
            for(int i=tid;i<TILE_U4;i+=256) xs[i]=inb[i];
        }
        __syncthreads();

        float hp[4][4];
        #pragma unroll
        for(int c=0;c<4;++c){ hp[c][0]=0.f;hp[c][1]=0.f;hp[c][2]=0.f;hp[c][3]=0.f; }

        #pragma unroll 1
        for(int t=0;t<32;++t){
            float Ar[4][4],Az[4][4],Ax[4][4],Ah[4][4];
            #pragma unroll
            for(int c=0;c<4;++c)
                #pragma unroll
                for(int e=0;e<4;++e){ Ar[c][e]=0.f;Az[c][e]=0.f;Ax[c][e]=0.f;Ah[c][e]=0.f; }

            #pragma unroll
            for(int kt=0;kt<4;++kt){
                uu ax[4],ah[4];
                ldsm4(ax, smb+SM_X+arow+kt*32);
                if(t) ldsm4(ah, smb+SM_H+arow+kt*32);
                #pragma unroll
                for(int ct=0;ct<4;++ct){
                    const uu nR=(uu)((u0w+ct*8)*144);
                    const uu nZ=nR+9216u;
                    const uu nN=nR+18432u;
                    uu b0[2],b1[2];
                    // r gate: X@Wih_r (+ H@Whh_r), weights hi+lo
                    ldsm2(b0, smb+SM_WI+nR+brow+kt*32);
                    ldsm2(b1, smb+SM_WI+27648+nR+brow+kt*32);
                    mma16816(Ar[ct],ax,b0); mma16816(Ar[ct],ax,b1);
                    if(t){
                        ldsm2(b0, smb+SM_WH+nR+brow+kt*32);
                        ldsm2(b1, smb+SM_WH+27648+nR+brow+kt*32);
                        mma16816(Ar[ct],ah,b0); mma16816(Ar[ct],ah,b1);
                    }
                    // z gate
                    ldsm2(b0, smb+SM_WI+nZ+brow+kt*32);
                    ldsm2(b1, smb+SM_WI+27648+nZ+brow+kt*32);
                    mma16816(Az[ct],ax,b0); mma16816(Az[ct],ax,b1);
                    if(t){
                        ldsm2(b0, smb+SM_WH+nZ+brow+kt*32);
                        ldsm2(b1, smb+SM_WH+27648+nZ+brow+kt*32);
                        mma16816(Az[ct],ah,b0); mma16816(Az[ct],ah,b1);
                    }
                    // xn (Wih only)
                    ldsm2(b0, smb+SM_WI+nN+brow+kt*32);
                    ldsm2(b1, smb+SM_WI+27648+nN+brow+kt*32);
                    mma16816(Ax[ct],ax,b0); mma16816(Ax[ct],ax,b1);
                    // hn (Whh only)
                    if(t){
                        ldsm2(b0, smb+SM_WH+nN+brow+kt*32);
                        ldsm2(b1, smb+SM_WH+27648+nN+brow+kt*32);
                        mma16816(Ah[ct],ah,b0); mma16816(Ah[ct],ah,b1);
                    }
                }
            }

            // prefetch / generate next X tile
            uint4 pf[3];
            uu gh[8];
            if(t<31){
                if(l==0){
                    float xv=xw[gr*32+t+1];
                    #pragma unroll
                    for(int i=0;i<8;++i){
                        int k=gc*16+i*2;
                        float v0=fmaxf(xv*sw[k]+sw[64+k],0.f);
                        float v1=fmaxf(xv*sw[k+1]+sw[64+k+1],0.f);
                        gh[i]=pack2h(v0,v1);
                    }
                } else {
                    const uint4* nx=inb+(size_t)(t+1)*TILE_U4;
                    #pragma unroll
                    for(int j=0;j<3;++j){ int idx=tid+j*256; if(idx<TILE_U4) pf[j]=nx[idx]; }
                }
            }

            // gates: fully in registers (m16n8k16 D layout)
            float hv[4][4];
            #pragma unroll
            for(int ct=0;ct<4;++ct){
                const int ue=u0w+ct*8+(lane&3)*2;
                #pragma unroll
                for(int e=0;e<4;++e){
                    const int u=ue+(e&1);
                    float ar=Ar[ct][e]+bias[u];
                    float az=Az[ct][e]+bias[64+u];
                    float ax2=Ax[ct][e]+bias[128+u];
                    float ah2=Ah[ct][e]+bias[192+u];
                    float tr=__expf(fminf(-ar,30.f));
                    float tz=__expf(fminf(-az,30.f));
                    float q=frcp((1.f+tr)*(1.f+tz));
                    float r=q*(1.f+tz), z=q*(1.f+tr);
                    float wv=ax2+r*ah2;
                    float tn=__expf(fminf(-2.f*wv,30.f));
                    float n=2.f*frcp(1.f+tn)-1.f;
                    float hn=z*(hp[ct][e]-n)+n;
                    hp[ct][e]=hn; hv[ct][e]=hn;
                }
            }

            __syncthreads();   // S1: all smem reads of step t complete

            const bool wout=(l<3);
            uu* oti=outb+(size_t)t*2304;
            #pragma unroll
            for(int ct=0;ct<4;++ct){
                const int ue=u0w+ct*8+(lane&3)*2;
                const int rA=r0w+(lane>>2);
                *(uu*)(smc+SM_H+rA*144+ue*2)    =pack2h(hv[ct][0],hv[ct][1]);
                *(uu*)(smc+SM_H+(rA+8)*144+ue*2)=pack2h(hv[ct][2],hv[ct][3]);
                if(wout){
                    oti[rA*36+(ue>>1)]    =pack2h(fmaxf(hv[ct][0],0.f),fmaxf(hv[ct][1],0.f));
                    oti[(rA+8)*36+(ue>>1)]=pack2h(fmaxf(hv[ct][2],0.f),fmaxf(hv[ct][3],0.f));
                }
            }
            if(t<31){
                if(l==0){
                    #pragma unroll
                    for(int i=0;i<8;++i){
                        int k=gc*16+i*2;
                        *(uu*)(smc+SM_X+gr*144+k*2)=gh[i];
                    }
                } else {
                    uint4* xs=(uint4*)(smc+SM_X);
                    #pragma unroll
                    for(int j=0;j<3;++j){ int idx=tid+j*256; if(idx<TILE_U4) xs[idx]=pf[j]; }
                }
            }
            __syncthreads();   // S2: writes visible for step t+1
        }
    }

    // ---- fused head: eps = relu(h31) @ W2 + b2 -> d_A, d_G -------------------
    // h31 (pre-relu fp16) is in SM_H [9216..18432). Scratch lives ONLY in the
    // dead weight regions: w2s/b2s in SM_WI, hr in SM_WH. No overlap with SM_H.
    float* w2s=(float*)(smc+SM_WI);             // 16 KB at 18432..34816
    float* b2s=(float*)(smc+SM_WI+16384);       // 256 B at 34816..35072
    float* hr =(float*)(smc+SM_WH);             // 64x65 f32 at 73728..90368
    for(int i=tid;i<4096;i+=256) w2s[i]=d_W2[i];
    if(tid<64) b2s[tid]=d_b2[tid];
    for(int i=tid;i<4096;i+=256){
        int m=i>>6, k=i&63;
        float v=__half2float(*(const __half*)(smc+SM_H+m*144+k*2));
        hr[m*65+k]=fmaxf(v,0.f);
    }
    __syncthreads();
    for(int i=tid;i<4096;i+=256){
        int m=i>>6, u=i&63;
        float a=b2s[u];
        #pragma unroll 8
        for(int k=0;k<64;++k) a+=hr[m*65+k]*w2s[k*64+u];
        int g=cta*MROWS+m;
        if(g<BS_TOT){
            if(u<HFAST) d_A[g*HFAST+u]=sigm(a);
            else        d_G[g*HFAST+u-HFAST]=a;
        }
    }
}

// ---- fuse: W2 = soW @ s2sW, b2 = sob @ s2sW + s2sb ----------------------------
__global__ void fuse_kernel(const float* __restrict__ soW, const float* __restrict__ sob,
                            const float* __restrict__ s2sW, const float* __restrict__ s2sb)
{
    int tid=threadIdx.x;
    for(int i=tid;i<4096;i+=256){
        int k=i>>6, v=i&63;
        float a=0.f;
        for(int u=0;u<64;++u) a+=soW[k*64+u]*s2sW[u*64+v];
        d_W2[i]=a;
    }
    if(tid<64){
        float a=s2sb[tid];
        for(int u=0;u<64;++u) a+=sob[u]*s2sW[u*64+tid];
        d_b2[tid]=a;
    }
}

// ---- fast path + overlap-add (verified) ----------------------------------------
__global__ void __launch_bounds__(256) fast_kernel(
    const float* __restrict__ x, const float* __restrict__ finW,
    const float* __restrict__ finb, const float* __restrict__ foutW,
    const float* __restrict__ foutb)
{
    int w=(blockIdx.x*blockDim.x+threadIdx.x)>>5;
    int h=threadIdx.x&31;
    if(w>=BS_TOT) return;
    int b=w/NF, f=w-b*NF;
    float A=d_A[w*HFAST+h], G=d_G[w*HFAST+h];
    float fw=__ldg(&finW[h]), fb=__ldg(&finb[h]);
    float fo=__ldg(&foutW[h]), fob=__ldg(&foutb[0]);
    const float* xp=x+b*T_LEN+f*16;
    float hsv=0.f;
    #pragma unroll
    for(int t=0;t<32;++t){
        float e=(xp[t]*fw+fb)*G;
        hsv=A*hsv+e;
        float y=hsv*fo;
        #pragma unroll
        for(int mm=16;mm;mm>>=1) y+=__shfl_xor_sync(0xffffffffu,y,mm);
        if(h==t) d_S[w*32+t]=y+fob;
    }
}
__global__ void __launch_bounds__(256) oadd_kernel(float* __restrict__ out)
{
    int idx=blockIdx.x*blockDim.x+threadIdx.x;
    if(idx>=B_SZ*T_LEN) return;
    int b=idx/T_LEN, i=idx-b*T_LEN;
    int f1=i>>4, j=i&15;
    float v=0.f;
    if(f1<NF) v+=d_S[(b*NF+f1)*32+j];
    if(f1>=1) v+=d_S[(b*NF+f1-1)*32+j+16];
    out[idx]=v;
}

extern "C" void kernel_launch(void* const* d_in, const int* in_sizes, int n_in,
                              void* d_out, int out_size)
{
    const float* x    =(const float*)d_in[0];
    const float* siW  =(const float*)d_in[1];
    const float* sib  =(const float*)d_in[2];
    const float* Wih  =(const float*)d_in[3];
    const float* Whh  =(const float*)d_in[4];
    const float* bih  =(const float*)d_in[5];
    const float* bhh  =(const float*)d_in[6];
    const float* soW  =(const float*)d_in[7];
    const float* sob  =(const float*)d_in[8];
    const float* s2sW =(const float*)d_in[9];
    const float* s2sb =(const float*)d_in[10];
    const float* finW =(const float*)d_in[11];
    const float* finb =(const float*)d_in[12];
    const float* foW  =(const float*)d_in[13];
    const float* fob  =(const float*)d_in[14];
    float* out=(float*)d_out;

    cudaFuncSetAttribute(slow_kernel, cudaFuncAttributeMaxDynamicSharedMemorySize, SMEM_SZ);
    fuse_kernel<<<1,256>>>(soW,sob,s2sW,s2sb);
    slow_kernel<<<NCTA,256,SMEM_SZ>>>(x,siW,sib,Wih,Whh,bih,bhh);
    fast_kernel<<<(BS_TOT*32+255)/256,256>>>(x,finW,finb,foW,fob);
    oadd_kernel<<<(B_SZ*T_LEN+255)/256,256>>>(out);
}

// round 14
// speedup vs baseline: 2.1502x; 1.3423x over previous
#include <cuda_runtime.h>
#include <cuda_fp16.h>
#include <math.h>
#include <stdint.h>

#define T_LEN 64000
#define B_SZ  2
#define NS    3999
#define NF    3999
#define BS_TOT (B_SZ*NS)
#define HFAST 32
#define NCTA  126
#define MROWS 64
#define TILE_U4 576             // uint4 per layer-IO tile (fp16 [64][72])

// smem byte offsets
#define SM_X   0                // X [64][72] fp16
#define SM_H   9216             // H [64][72] fp16
#define SM_WI  18432            // Wih^T [192][72] fp16 (single)
#define SM_WH  46080            // Whh^T [192][72] fp16 (single)
#define SM_BIAS 73728           // 256 floats
#define SM_XW   74752           // x windows [64][32] f32
#define SM_SIW  82944           // siW[64], sib[64]
#define SMEM_SZ 83456

__device__ uint4 d_lay[2][(size_t)NCTA*32*TILE_U4];
__device__ float d_W2[64*64];
__device__ float d_b2[64];
__device__ float d_A[BS_TOT*HFAST];
__device__ float d_G[BS_TOT*HFAST];
__device__ float d_S[BS_TOT*32];

typedef unsigned uu;

__device__ __forceinline__ uu s2u(const void* p){
    uu a; asm("{.reg .u64 t; cvta.to.shared.u64 t,%1; cvt.u32.u64 %0,t;}":"=r"(a):"l"(p)); return a;
}
__device__ __forceinline__ void ldsm4(uu* r, uu a){
    asm volatile("ldmatrix.sync.aligned.m8n8.x4.shared.b16 {%0,%1,%2,%3},[%4];"
        :"=r"(r[0]),"=r"(r[1]),"=r"(r[2]),"=r"(r[3]):"r"(a));
}
__device__ __forceinline__ void ldsm2(uu* r, uu a){
    asm volatile("ldmatrix.sync.aligned.m8n8.x2.shared.b16 {%0,%1},[%2];"
        :"=r"(r[0]),"=r"(r[1]):"r"(a));
}
__device__ __forceinline__ void mma16816(float* d, const uu* a, const uu* b){
    asm volatile("mma.sync.aligned.m16n8k16.row.col.f32.f16.f16.f32 "
        "{%0,%1,%2,%3},{%4,%5,%6,%7},{%8,%9},{%0,%1,%2,%3};"
        :"+f"(d[0]),"+f"(d[1]),"+f"(d[2]),"+f"(d[3])
        :"r"(a[0]),"r"(a[1]),"r"(a[2]),"r"(a[3]),"r"(b[0]),"r"(b[1]));
}
__device__ __forceinline__ float frcp(float x){
    float r; asm("rcp.approx.f32 %0,%1;":"=f"(r):"f"(x)); return r;
}
__device__ __forceinline__ uu pack2h(float a, float b){
    __half2 h=__floats2half2_rn(a,b); return *(uu*)&h;
}
__device__ __forceinline__ float sigm(float x){ return frcp(1.0f+__expf(fminf(-x,30.f))); }

// ---- slow: mma.sync fp16 GRU, fused prep+head --------------------------------
__global__ void __launch_bounds__(256,1) slow_kernel(
    const float* __restrict__ x,
    const float* __restrict__ siW, const float* __restrict__ sib,
    const float* __restrict__ Wih, const float* __restrict__ Whh,
    const float* __restrict__ bih, const float* __restrict__ bhh)
{
    extern __shared__ unsigned char smc[];
    const int tid=threadIdx.x, w=tid>>5, lane=tid&31;
    const int mw=w&3, uw=w>>2;
    const int r0w=mw*16, u0w=uw*32;
    const int cta=blockIdx.x;
    const uu smb=s2u(smc);
    float* bias=(float*)(smc+SM_BIAS);
    float* xw=(float*)(smc+SM_XW);
    float* sw=(float*)(smc+SM_SIW);

    const uu arow=(uu)((r0w+(lane&15))*144 + ((lane>>4)&1)*16);   // A: X/H tiles
    const uu brow=(uu)((lane&7)*144 + ((lane>>3)&1)*16);          // B: W tiles

    // stage x windows + siW/sib (once per CTA)
    for(int i=tid;i<2048;i+=256){
        int r=i>>5, tt=i&31;
        int g=cta*MROWS+r;
        float v=0.f;
        if(g<BS_TOT){ int b=g/NS, s=g-b*NS; v=x[b*T_LEN+s*16+tt]; }
        xw[i]=v;
    }
    if(tid<64){ sw[tid]=siW[tid]; sw[64+tid]=sib[tid]; }
    __syncthreads();

    const int gr=tid>>2, gc=tid&3;   // layer-0 generator assignment

    for(int l=0;l<4;++l){
        const uint4* inb = d_lay[l&1] + (size_t)cta*32*TILE_U4;
        uu* outb = (uu*)(d_lay[(l+1)&1] + (size_t)cta*32*TILE_U4);

        // stage weights transposed [n][k] fp16 (single)
        for(int i=tid;i<12288;i+=256){
            int k=i/192, n=i-k*192;
            uu off=(uu)(n*144+k*2);
            *(__half*)(smc+SM_WI+off)=__float2half_rn(Wih[l*12288+i]);
            *(__half*)(smc+SM_WH+off)=__float2half_rn(Whh[l*12288+i]);
        }
        if(tid<128)      bias[tid]=bih[l*192+tid]+bhh[l*192+tid];   // r,z combined
        else if(tid<192) bias[tid]=bih[l*192+tid];                  // xn (cols 128..191)
        else             bias[tid]=bhh[l*192+tid-64];               // hn (cols 128..191)

        // stage X(0)
        if(l==0){
            float xv=xw[gr*32+0];
            #pragma unroll
            for(int i=0;i<8;++i){
                int k=gc*16+i*2;
                float v0=fmaxf(xv*sw[k]+sw[64+k],0.f);
                float v1=fmaxf(xv*sw[k+1]+sw[64+k+1],0.f);
                *(uu*)(smc+SM_X+gr*144+k*2)=pack2h(v0,v1);
            }
        } else {
            uint4* xs=(uint4*)(smc+SM_X);
            for(int i=tid;i<TILE_U4;i+=256) xs[i]=inb[i];
        }
        __syncthreads();

        float hp[4][4];
        #pragma unroll
        for(int c=0;c<4;++c){ hp[c][0]=0.f;hp[c][1]=0.f;hp[c][2]=0.f;hp[c][3]=0.f; }

        #pragma unroll 1
        for(int t=0;t<32;++t){
            float Ar[4][4],Az[4][4],Ax[4][4],Ah[4][4];
            #pragma unroll
            for(int c=0;c<4;++c)
                #pragma unroll
                for(int e=0;e<4;++e){ Ar[c][e]=0.f;Az[c][e]=0.f;Ax[c][e]=0.f;Ah[c][e]=0.f; }

            #pragma unroll
            for(int kt=0;kt<4;++kt){
                uu ax[4],ah[4];
                ldsm4(ax, smb+SM_X+arow+kt*32);
                if(t) ldsm4(ah, smb+SM_H+arow+kt*32);
                #pragma unroll
                for(int ct=0;ct<4;++ct){
                    const uu nR=(uu)((u0w+ct*8)*144);
                    const uu nZ=nR+9216u;
                    const uu nN=nR+18432u;
                    uu b0[2];
                    // r gate
                    ldsm2(b0, smb+SM_WI+nR+brow+kt*32);
                    mma16816(Ar[ct],ax,b0);
                    if(t){
                        ldsm2(b0, smb+SM_WH+nR+brow+kt*32);
                        mma16816(Ar[ct],ah,b0);
                    }
                    // z gate
                    ldsm2(b0, smb+SM_WI+nZ+brow+kt*32);
                    mma16816(Az[ct],ax,b0);
                    if(t){
                        ldsm2(b0, smb+SM_WH+nZ+brow+kt*32);
                        mma16816(Az[ct],ah,b0);
                    }
                    // xn (Wih only)
                    ldsm2(b0, smb+SM_WI+nN+brow+kt*32);
                    mma16816(Ax[ct],ax,b0);
                    // hn (Whh only)
                    if(t){
                        ldsm2(b0, smb+SM_WH+nN+brow+kt*32);
                        mma16816(Ah[ct],ah,b0);
                    }
                }
            }

            // prefetch / generate next X tile
            uint4 pf[3];
            uu gh[8];
            if(t<31){
                if(l==0){
                    float xv=xw[gr*32+t+1];
                    #pragma unroll
                    for(int i=0;i<8;++i){
                        int k=gc*16+i*2;
                        float v0=fmaxf(xv*sw[k]+sw[64+k],0.f);
                        float v1=fmaxf(xv*sw[k+1]+sw[64+k+1],0.f);
                        gh[i]=pack2h(v0,v1);
                    }
                } else {
                    const uint4* nx=inb+(size_t)(t+1)*TILE_U4;
                    #pragma unroll
                    for(int j=0;j<3;++j){ int idx=tid+j*256; if(idx<TILE_U4) pf[j]=nx[idx]; }
                }
            }

            // gates: fully in registers (m16n8k16 D layout)
            float hv[4][4];
            #pragma unroll
            for(int ct=0;ct<4;++ct){
                const int ue=u0w+ct*8+(lane&3)*2;
                #pragma unroll
                for(int e=0;e<4;++e){
                    const int u=ue+(e&1);
                    float ar=Ar[ct][e]+bias[u];
                    float az=Az[ct][e]+bias[64+u];
                    float ax2=Ax[ct][e]+bias[128+u];
                    float ah2=Ah[ct][e]+bias[192+u];
                    float tr=__expf(fminf(-ar,30.f));
                    float tz=__expf(fminf(-az,30.f));
                    float q=frcp((1.f+tr)*(1.f+tz));
                    float r=q*(1.f+tz), z=q*(1.f+tr);
                    float wv=ax2+r*ah2;
                    float tn=__expf(fminf(-2.f*wv,30.f));
                    float n=2.f*frcp(1.f+tn)-1.f;
                    float hn=z*(hp[ct][e]-n)+n;
                    hp[ct][e]=hn; hv[ct][e]=hn;
                }
            }

            __syncthreads();   // S1: all smem reads of step t complete

            const bool wout=(l<3);
            uu* oti=outb+(size_t)t*2304;
            #pragma unroll
            for(int ct=0;ct<4;++ct){
                const int ue=u0w+ct*8+(lane&3)*2;
                const int rA=r0w+(lane>>2);
                *(uu*)(smc+SM_H+rA*144+ue*2)    =pack2h(hv[ct][0],hv[ct][1]);
                *(uu*)(smc+SM_H+(rA+8)*144+ue*2)=pack2h(hv[ct][2],hv[ct][3]);
                if(wout){
                    oti[rA*36+(ue>>1)]    =pack2h(fmaxf(hv[ct][0],0.f),fmaxf(hv[ct][1],0.f));
                    oti[(rA+8)*36+(ue>>1)]=pack2h(fmaxf(hv[ct][2],0.f),fmaxf(hv[ct][3],0.f));
                }
            }
            if(t<31){
                if(l==0){
                    #pragma unroll
                    for(int i=0;i<8;++i){
                        int k=gc*16+i*2;
                        *(uu*)(smc+SM_X+gr*144+k*2)=gh[i];
                    }
                } else {
                    uint4* xs=(uint4*)(smc+SM_X);
                    #pragma unroll
                    for(int j=0;j<3;++j){ int idx=tid+j*256; if(idx<TILE_U4) xs[idx]=pf[j]; }
                }
            }
            __syncthreads();   // S2: writes visible for step t+1
        }
    }

    // ---- fused head: eps = relu(h31) @ W2 + b2 -> d_A, d_G -------------------
    // h31 (pre-relu fp16) in SM_H [9216..18432). Scratch in dead weight regions.
    float* w2s=(float*)(smc+SM_WI);             // 16 KB at 18432..34816
    float* b2s=(float*)(smc+SM_WI+16384);       // 256 B at 34816..35072
    float* hr =(float*)(smc+SM_WH);             // 64x65 f32 at 46080..62720
    for(int i=tid;i<4096;i+=256) w2s[i]=d_W2[i];
    if(tid<64) b2s[tid]=d_b2[tid];
    for(int i=tid;i<4096;i+=256){
        int m=i>>6, k=i&63;
        float v=__half2float(*(const __half*)(smc+SM_H+m*144+k*2));
        hr[m*65+k]=fmaxf(v,0.f);
    }
    __syncthreads();
    for(int i=tid;i<4096;i+=256){
        int m=i>>6, u=i&63;
        float a=b2s[u];
        #pragma unroll 8
        for(int k=0;k<64;++k) a+=hr[m*65+k]*w2s[k*64+u];
        int g=cta*MROWS+m;
        if(g<BS_TOT){
            if(u<HFAST) d_A[g*HFAST+u]=sigm(a);
            else        d_G[g*HFAST+u-HFAST]=a;
        }
    }
}

// ---- fuse: W2 = soW @ s2sW, b2 = sob @ s2sW + s2sb ----------------------------
__global__ void fuse_kernel(const float* __restrict__ soW, const float* __restrict__ sob,
                            const float* __restrict__ s2sW, const float* __restrict__ s2sb)
{
    int tid=threadIdx.x;
    for(int i=tid;i<4096;i+=256){
        int k=i>>6, v=i&63;
        float a=0.f;
        for(int u=0;u<64;++u) a+=soW[k*64+u]*s2sW[u*64+v];
        d_W2[i]=a;
    }
    if(tid<64){
        float a=s2sb[tid];
        for(int u=0;u<64;++u) a+=sob[u]*s2sW[u*64+tid];
        d_b2[tid]=a;
    }
}

// ---- fast path + overlap-add (verified) ----------------------------------------
__global__ void __launch_bounds__(256) fast_kernel(
    const float* __restrict__ x, const float* __restrict__ finW,
    const float* __restrict__ finb, const float* __restrict__ foutW,
    const float* __restrict__ foutb)
{
    int w=(blockIdx.x*blockDim.x+threadIdx.x)>>5;
    int h=threadIdx.x&31;
    if(w>=BS_TOT) return;
    int b=w/NF, f=w-b*NF;
    float A=d_A[w*HFAST+h], G=d_G[w*HFAST+h];
    float fw=__ldg(&finW[h]), fb=__ldg(&finb[h]);
    float fo=__ldg(&foutW[h]), fob=__ldg(&foutb[0]);
    const float* xp=x+b*T_LEN+f*16;
    float hsv=0.f;
    #pragma unroll
    for(int t=0;t<32;++t){
        float e=(xp[t]*fw+fb)*G;
        hsv=A*hsv+e;
        float y=hsv*fo;
        #pragma unroll
        for(int mm=16;mm;mm>>=1) y+=__shfl_xor_sync(0xffffffffu,y,mm);
        if(h==t) d_S[w*32+t]=y+fob;
    }
}
__global__ void __launch_bounds__(256) oadd_kernel(float* __restrict__ out)
{
    int idx=blockIdx.x*blockDim.x+threadIdx.x;
    if(idx>=B_SZ*T_LEN) return;
    int b=idx/T_LEN, i=idx-b*T_LEN;
    int f1=i>>4, j=i&15;
    float v=0.f;
    if(f1<NF) v+=d_S[(b*NF+f1)*32+j];
    if(f1>=1) v+=d_S[(b*NF+f1-1)*32+j+16];
    out[idx]=v;
}

extern "C" void kernel_launch(void* const* d_in, const int* in_sizes, int n_in,
                              void* d_out, int out_size)
{
    const float* x    =(const float*)d_in[0];
    const float* siW  =(const float*)d_in[1];
    const float* sib  =(const float*)d_in[2];
    const float* Wih  =(const float*)d_in[3];
    const float* Whh  =(const float*)d_in[4];
    const float* bih  =(const float*)d_in[5];
    const float* bhh  =(const float*)d_in[6];
    const float* soW  =(const float*)d_in[7];
    const float* sob  =(const float*)d_in[8];
    const float* s2sW =(const float*)d_in[9];
    const float* s2sb =(const float*)d_in[10];
    const float* finW =(const float*)d_in[11];
    const float* finb =(const float*)d_in[12];
    const float* foW  =(const float*)d_in[13];
    const float* fob  =(const float*)d_in[14];
    float* out=(float*)d_out;

    cudaFuncSetAttribute(slow_kernel, cudaFuncAttributeMaxDynamicSharedMemorySize, SMEM_SZ);
    fuse_kernel<<<1,256>>>(soW,sob,s2sW,s2sb);
    slow_kernel<<<NCTA,256,SMEM_SZ>>>(x,siW,sib,Wih,Whh,bih,bhh);
    fast_kernel<<<(BS_TOT*32+255)/256,256>>>(x,finW,finb,foW,fob);
    oadd_kernel<<<(B_SZ*T_LEN+255)/256,256>>>(out);
}

// round 15
// speedup vs baseline: 2.1896x; 1.0183x over previous
#include <cuda_runtime.h>
#include <cuda_fp16.h>
#include <math.h>
#include <stdint.h>

#define T_LEN 64000
#define B_SZ  2
#define NS    3999
#define NF    3999
#define BS_TOT (B_SZ*NS)
#define HFAST 32
#define NCTA  126
#define MROWS 64
#define TILE_U4 576             // uint4 per layer-IO tile (fp16 [64][72])

// smem byte offsets
#define SM_X   0                // X [64][72] fp16
#define SM_H   9216             // H [64][72] fp16
#define SM_WI  18432            // Wih^T [192][72] fp16
#define SM_WH  46080            // Whh^T [192][72] fp16
#define SM_BIAS 73728           // 256 floats
#define SM_XW   74752           // x windows [64][32] f32
#define SM_SIW  82944           // siW[64], sib[64]
#define SMEM_SZ 83456

__device__ uint4 d_lay[2][(size_t)NCTA*32*TILE_U4];
__device__ float d_W2[64*64];
__device__ float d_b2[64];
__device__ float d_A[BS_TOT*HFAST];
__device__ float d_G[BS_TOT*HFAST];
__device__ float d_S[BS_TOT*32];

typedef unsigned uu;

__device__ __forceinline__ uu s2u(const void* p){
    uu a; asm("{.reg .u64 t; cvta.to.shared.u64 t,%1; cvt.u32.u64 %0,t;}":"=r"(a):"l"(p)); return a;
}
__device__ __forceinline__ void ldsm4(uu* r, uu a){
    asm volatile("ldmatrix.sync.aligned.m8n8.x4.shared.b16 {%0,%1,%2,%3},[%4];"
        :"=r"(r[0]),"=r"(r[1]),"=r"(r[2]),"=r"(r[3]):"r"(a));
}
__device__ __forceinline__ void ldsm2(uu* r, uu a){
    asm volatile("ldmatrix.sync.aligned.m8n8.x2.shared.b16 {%0,%1},[%2];"
        :"=r"(r[0]),"=r"(r[1]):"r"(a));
}
__device__ __forceinline__ void mma16816(float* d, const uu* a, const uu* b){
    asm volatile("mma.sync.aligned.m16n8k16.row.col.f32.f16.f16.f32 "
        "{%0,%1,%2,%3},{%4,%5,%6,%7},{%8,%9},{%0,%1,%2,%3};"
        :"+f"(d[0]),"+f"(d[1]),"+f"(d[2]),"+f"(d[3])
        :"r"(a[0]),"r"(a[1]),"r"(a[2]),"r"(a[3]),"r"(b[0]),"r"(b[1]));
}
__device__ __forceinline__ float frcp(float x){
    float r; asm("rcp.approx.f32 %0,%1;":"=f"(r):"f"(x)); return r;
}
__device__ __forceinline__ uu pack2h(float a, float b){
    __half2 h=__floats2half2_rn(a,b); return *(uu*)&h;
}
__device__ __forceinline__ float sigm(float x){ return frcp(1.0f+__expf(fminf(-x,30.f))); }

// ---- slow: mma.sync fp16 GRU, fused prep+head, software-pipelined loads ------
__global__ void __launch_bounds__(256,1) slow_kernel(
    const float* __restrict__ x,
    const float* __restrict__ siW, const float* __restrict__ sib,
    const float* __restrict__ Wih, const float* __restrict__ Whh,
    const float* __restrict__ bih, const float* __restrict__ bhh)
{
    extern __shared__ unsigned char smc[];
    const int tid=threadIdx.x, w=tid>>5, lane=tid&31;
    const int mw=w&3, uw=w>>2;
    const int r0w=mw*16, u0w=uw*32;
    const int cta=blockIdx.x;
    const uu smb=s2u(smc);
    float* bias=(float*)(smc+SM_BIAS);
    float* xw=(float*)(smc+SM_XW);
    float* sw=(float*)(smc+SM_SIW);

    const uu arow=(uu)((r0w+(lane&15))*144 + ((lane>>4)&1)*16);   // A: X/H tiles
    const uu brow=(uu)((lane&7)*144 + ((lane>>3)&1)*16);          // B: W tiles

    // stage x windows + siW/sib (once per CTA)
    for(int i=tid;i<2048;i+=256){
        int r=i>>5, tt=i&31;
        int g=cta*MROWS+r;
        float v=0.f;
        if(g<BS_TOT){ int b=g/NS, s=g-b*NS; v=x[b*T_LEN+s*16+tt]; }
        xw[i]=v;
    }
    if(tid<64){ sw[tid]=siW[tid]; sw[64+tid]=sib[tid]; }
    __syncthreads();

    const int gr=tid>>2, gc=tid&3;   // layer-0 generator assignment

    for(int l=0;l<4;++l){
        const uint4* inb = d_lay[l&1] + (size_t)cta*32*TILE_U4;
        uu* outb = (uu*)(d_lay[(l+1)&1] + (size_t)cta*32*TILE_U4);

        // stage weights transposed [n][k] fp16
        for(int i=tid;i<12288;i+=256){
            int k=i/192, n=i-k*192;
            uu off=(uu)(n*144+k*2);
            *(__half*)(smc+SM_WI+off)=__float2half_rn(Wih[l*12288+i]);
            *(__half*)(smc+SM_WH+off)=__float2half_rn(Whh[l*12288+i]);
        }
        if(tid<128)      bias[tid]=bih[l*192+tid]+bhh[l*192+tid];   // r,z combined
        else if(tid<192) bias[tid]=bih[l*192+tid];                  // xn (cols 128..191)
        else             bias[tid]=bhh[l*192+tid-64];               // hn (cols 128..191)

        // stage X(0)
        if(l==0){
            float xv=xw[gr*32+0];
            #pragma unroll
            for(int i=0;i<8;++i){
                int k=gc*16+i*2;
                float v0=fmaxf(xv*sw[k]+sw[64+k],0.f);
                float v1=fmaxf(xv*sw[k+1]+sw[64+k+1],0.f);
                *(uu*)(smc+SM_X+gr*144+k*2)=pack2h(v0,v1);
            }
        } else {
            uint4* xs=(uint4*)(smc+SM_X);
            for(int i=tid;i<TILE_U4;i+=256) xs[i]=inb[i];
        }
        __syncthreads();

        float hp[4][4];
        #pragma unroll
        for(int c=0;c<4;++c){ hp[c][0]=0.f;hp[c][1]=0.f;hp[c][2]=0.f;hp[c][3]=0.f; }

        #pragma unroll 1
        for(int t=0;t<32;++t){
            float Ar[4][4],Az[4][4],Ax[4][4],Ah[4][4];
            #pragma unroll
            for(int c=0;c<4;++c)
                #pragma unroll
                for(int e=0;e<4;++e){ Ar[c][e]=0.f;Az[c][e]=0.f;Ax[c][e]=0.f;Ah[c][e]=0.f; }

            #pragma unroll
            for(int kt=0;kt<4;++kt){
                uu ax[4],ah[4];
                uu bb[48];     // distinct regs: [ct][mat(6)][2]
                // ---- issue ALL loads for this kt first (no WAR chains) ------
                ldsm4(ax, smb+SM_X+arow+kt*32);
                if(t) ldsm4(ah, smb+SM_H+arow+kt*32);
                #pragma unroll
                for(int ct=0;ct<4;++ct){
                    const uu nR=(uu)((u0w+ct*8)*144);
                    ldsm2(&bb[ct*12+0], smb+SM_WI+nR+brow+kt*32);            // Wi_r
                    ldsm2(&bb[ct*12+2], smb+SM_WI+nR+9216u+brow+kt*32);      // Wi_z
                    ldsm2(&bb[ct*12+4], smb+SM_WI+nR+18432u+brow+kt*32);     // Wi_n
                    if(t){
                        ldsm2(&bb[ct*12+6],  smb+SM_WH+nR+brow+kt*32);       // Wh_r
                        ldsm2(&bb[ct*12+8],  smb+SM_WH+nR+9216u+brow+kt*32); // Wh_z
                        ldsm2(&bb[ct*12+10], smb+SM_WH+nR+18432u+brow+kt*32);// Wh_n
                    }
                }
                // ---- then all MMAs (operands already in flight/ready) -------
                #pragma unroll
                for(int ct=0;ct<4;++ct){
                    mma16816(Ar[ct],ax,&bb[ct*12+0]);
                    mma16816(Az[ct],ax,&bb[ct*12+2]);
                    mma16816(Ax[ct],ax,&bb[ct*12+4]);
                    if(t){
                        mma16816(Ar[ct],ah,&bb[ct*12+6]);
                        mma16816(Az[ct],ah,&bb[ct*12+8]);
                        mma16816(Ah[ct],ah,&bb[ct*12+10]);
                    }
                }
            }

            // prefetch / generate next X tile
            uint4 pf[3];
            uu gh[8];
            if(t<31){
                if(l==0){
                    float xv=xw[gr*32+t+1];
                    #pragma unroll
                    for(int i=0;i<8;++i){
                        int k=gc*16+i*2;
                        float v0=fmaxf(xv*sw[k]+sw[64+k],0.f);
                        float v1=fmaxf(xv*sw[k+1]+sw[64+k+1],0.f);
                        gh[i]=pack2h(v0,v1);
                    }
                } else {
                    const uint4* nx=inb+(size_t)(t+1)*TILE_U4;
                    #pragma unroll
                    for(int j=0;j<3;++j){ int idx=tid+j*256; if(idx<TILE_U4) pf[j]=nx[idx]; }
                }
            }

            // gates: fully in registers (m16n8k16 D layout)
            float hv[4][4];
            #pragma unroll
            for(int ct=0;ct<4;++ct){
                const int ue=u0w+ct*8+(lane&3)*2;
                #pragma unroll
                for(int e=0;e<4;++e){
                    const int u=ue+(e&1);
                    float ar=Ar[ct][e]+bias[u];
                    float az=Az[ct][e]+bias[64+u];
                    float ax2=Ax[ct][e]+bias[128+u];
                    float ah2=Ah[ct][e]+bias[192+u];
                    float tr=__expf(fminf(-ar,30.f));
                    float tz=__expf(fminf(-az,30.f));
                    float q=frcp((1.f+tr)*(1.f+tz));
                    float r=q*(1.f+tz), z=q*(1.f+tr);
                    float wv=ax2+r*ah2;
                    float tn=__expf(fminf(-2.f*wv,30.f));
                    float n=2.f*frcp(1.f+tn)-1.f;
                    float hn=z*(hp[ct][e]-n)+n;
                    hp[ct][e]=hn; hv[ct][e]=hn;
                }
            }

            __syncthreads();   // S1: all smem reads of step t complete

            const bool wout=(l<3);
            uu* oti=outb+(size_t)t*2304;
            #pragma unroll
            for(int ct=0;ct<4;++ct){
                const int ue=u0w+ct*8+(lane&3)*2;
                const int rA=r0w+(lane>>2);
                *(uu*)(smc+SM_H+rA*144+ue*2)    =pack2h(hv[ct][0],hv[ct][1]);
                *(uu*)(smc+SM_H+(rA+8)*144+ue*2)=pack2h(hv[ct][2],hv[ct][3]);
                if(wout){
                    oti[rA*36+(ue>>1)]    =pack2h(fmaxf(hv[ct][0],0.f),fmaxf(hv[ct][1],0.f));
                    oti[(rA+8)*36+(ue>>1)]=pack2h(fmaxf(hv[ct][2],0.f),fmaxf(hv[ct][3],0.f));
                }
            }
            if(t<31){
                if(l==0){
                    #pragma unroll
                    for(int i=0;i<8;++i){
                        int k=gc*16+i*2;
                        *(uu*)(smc+SM_X+gr*144+k*2)=gh[i];
                    }
                } else {
                    uint4* xs=(uint4*)(smc+SM_X);
                    #pragma unroll
                    for(int j=0;j<3;++j){ int idx=tid+j*256; if(idx<TILE_U4) xs[idx]=pf[j]; }
                }
            }
            __syncthreads();   // S2: writes visible for step t+1
        }
    }

    // ---- fused head: eps = relu(h31) @ W2 + b2 -> d_A, d_G -------------------
    float* w2s=(float*)(smc+SM_WI);             // 16 KB at 18432..34816
    float* b2s=(float*)(smc+SM_WI+16384);       // 256 B at 34816..35072
    float* hr =(float*)(smc+SM_WH);             // 64x65 f32 at 46080..62720
    for(int i=tid;i<4096;i+=256) w2s[i]=d_W2[i];
    if(tid<64) b2s[tid]=d_b2[tid];
    for(int i=tid;i<4096;i+=256){
        int m=i>>6, k=i&63;
        float v=__half2float(*(const __half*)(smc+SM_H+m*144+k*2));
        hr[m*65+k]=fmaxf(v,0.f);
    }
    __syncthreads();
    for(int i=tid;i<4096;i+=256){
        int m=i>>6, u=i&63;
        float a=b2s[u];
        #pragma unroll 8
        for(int k=0;k<64;++k) a+=hr[m*65+k]*w2s[k*64+u];
        int g=cta*MROWS+m;
        if(g<BS_TOT){
            if(u<HFAST) d_A[g*HFAST+u]=sigm(a);
            else        d_G[g*HFAST+u-HFAST]=a;
        }
    }
}

// ---- fuse: W2 = soW @ s2sW, b2 = sob @ s2sW + s2sb ----------------------------
__global__ void fuse_kernel(const float* __restrict__ soW, const float* __restrict__ sob,
                            const float* __restrict__ s2sW, const float* __restrict__ s2sb)
{
    int tid=threadIdx.x;
    for(int i=tid;i<4096;i+=256){
        int k=i>>6, v=i&63;
        float a=0.f;
        for(int u=0;u<64;++u) a+=soW[k*64+u]*s2sW[u*64+v];
        d_W2[i]=a;
    }
    if(tid<64){
        float a=s2sb[tid];
        for(int u=0;u<64;++u) a+=sob[u]*s2sW[u*64+tid];
        d_b2[tid]=a;
    }
}

// ---- fast path + overlap-add (verified) ----------------------------------------
__global__ void __launch_bounds__(256) fast_kernel(
    const float* __restrict__ x, const float* __restrict__ finW,
    const float* __restrict__ finb, const float* __restrict__ foutW,
    const float* __restrict__ foutb)
{
    int w=(blockIdx.x*blockDim.x+threadIdx.x)>>5;
    int h=threadIdx.x&31;
    if(w>=BS_TOT) return;
    int b=w/NF, f=w-b*NF;
    float A=d_A[w*HFAST+h], G=d_G[w*HFAST+h];
    float fw=__ldg(&finW[h]), fb=__ldg(&finb[h]);
    float fo=__ldg(&foutW[h]), fob=__ldg(&foutb[0]);
    const float* xp=x+b*T_LEN+f*16;
    float hsv=0.f;
    #pragma unroll
    for(int t=0;t<32;++t){
        float e=(xp[t]*fw+fb)*G;
        hsv=A*hsv+e;
        float y=hsv*fo;
        #pragma unroll
        for(int mm=16;mm;mm>>=1) y+=__shfl_xor_sync(0xffffffffu,y,mm);
        if(h==t) d_S[w*32+t]=y+fob;
    }
}
__global__ void __launch_bounds__(256) oadd_kernel(float* __restrict__ out)
{
    int idx=blockIdx.x*blockDim.x+threadIdx.x;
    if(idx>=B_SZ*T_LEN) return;
    int b=idx/T_LEN, i=idx-b*T_LEN;
    int f1=i>>4, j=i&15;
    float v=0.f;
    if(f1<NF) v+=d_S[(b*NF+f1)*32+j];
    if(f1>=1) v+=d_S[(b*NF+f1-1)*32+j+16];
    out[idx]=v;
}

extern "C" void kernel_launch(void* const* d_in, const int* in_sizes, int n_in,
                              void* d_out, int out_size)
{
    const float* x    =(const float*)d_in[0];
    const float* siW  =(const float*)d_in[1];
    const float* sib  =(const float*)d_in[2];
    const float* Wih  =(const float*)d_in[3];
    const float* Whh  =(const float*)d_in[4];
    const float* bih  =(const float*)d_in[5];
    const float* bhh  =(const float*)d_in[6];
    const float* soW  =(const float*)d_in[7];
    const float* sob  =(const float*)d_in[8];
    const float* s2sW =(const float*)d_in[9];
    const float* s2sb =(const float*)d_in[10];
    const float* finW =(const float*)d_in[11];
    const float* finb =(const float*)d_in[12];
    const float* foW  =(const float*)d_in[13];
    const float* fob  =(const float*)d_in[14];
    float* out=(float*)d_out;

    cudaFuncSetAttribute(slow_kernel, cudaFuncAttributeMaxDynamicSharedMemorySize, SMEM_SZ);
    fuse_kernel<<<1,256>>>(soW,sob,s2sW,s2sb);
    slow_kernel<<<NCTA,256,SMEM_SZ>>>(x,siW,sib,Wih,Whh,bih,bhh);
    fast_kernel<<<(BS_TOT*32+255)/256,256>>>(x,finW,finb,foW,fob);
    oadd_kernel<<<(B_SZ*T_LEN+255)/256,256>>>(out);
}

// round 16
// speedup vs baseline: 2.5503x; 1.1647x over previous
#include <cuda_runtime.h>
#include <cuda_fp16.h>
#include <math.h>
#include <stdint.h>

#define T_LEN 64000
#define B_SZ  2
#define NS    3999
#define NF    3999
#define BS_TOT (B_SZ*NS)
#define HFAST 32
#define NCTA  126
#define MROWS 64
#define TILE_U4 576             // uint4 per layer-IO tile (fp16 [64][72])

// smem byte offsets
#define SM_X   0                // X [64][72] fp16
#define SM_H   9216             // H [64][72] fp16
#define SM_WI  18432            // Wih^T [192][72] fp16
#define SM_WH  46080            // Whh^T [192][72] fp16
#define SM_BIAS 73728           // 256 floats
#define SM_XW   74752           // x windows [64][32] f32
#define SM_SIW  82944           // siW[64], sib[64]
#define SMEM_SZ 83456

__device__ uint4 d_lay[2][(size_t)NCTA*32*TILE_U4];
__device__ float d_W2[64*64];
__device__ float d_b2[64];
__device__ float d_A[BS_TOT*HFAST];
__device__ float d_G[BS_TOT*HFAST];
__device__ float d_S[BS_TOT*32];

typedef unsigned uu;

__device__ __forceinline__ uu s2u(const void* p){
    uu a; asm("{.reg .u64 t; cvta.to.shared.u64 t,%1; cvt.u32.u64 %0,t;}":"=r"(a):"l"(p)); return a;
}
__device__ __forceinline__ void ldsm4(uu* r, uu a){
    asm volatile("ldmatrix.sync.aligned.m8n8.x4.shared.b16 {%0,%1,%2,%3},[%4];"
        :"=r"(r[0]),"=r"(r[1]),"=r"(r[2]),"=r"(r[3]):"r"(a));
}
__device__ __forceinline__ void ldsm2(uu* r, uu a){
    asm volatile("ldmatrix.sync.aligned.m8n8.x2.shared.b16 {%0,%1},[%2];"
        :"=r"(r[0]),"=r"(r[1]):"r"(a));
}
__device__ __forceinline__ void mma16816(float* d, const uu* a, const uu* b){
    asm volatile("mma.sync.aligned.m16n8k16.row.col.f32.f16.f16.f32 "
        "{%0,%1,%2,%3},{%4,%5,%6,%7},{%8,%9},{%0,%1,%2,%3};"
        :"+f"(d[0]),"+f"(d[1]),"+f"(d[2]),"+f"(d[3])
        :"r"(a[0]),"r"(a[1]),"r"(a[2]),"r"(a[3]),"r"(b[0]),"r"(b[1]));
}
__device__ __forceinline__ float tanh_ap(float x){
    float r; asm("tanh.approx.f32 %0,%1;":"=f"(r):"f"(x)); return r;
}
__device__ __forceinline__ uu pack2h(float a, float b){
    __half2 h=__floats2half2_rn(a,b); return *(uu*)&h;
}
__device__ __forceinline__ float sigm(float x){ return 0.5f+0.5f*tanh_ap(0.5f*x); }

// ---- slow: mma.sync fp16 GRU, fused prep+head, MUFU.TANH gates ---------------
__global__ void __launch_bounds__(256,1) slow_kernel(
    const float* __restrict__ x,
    const float* __restrict__ siW, const float* __restrict__ sib,
    const float* __restrict__ Wih, const float* __restrict__ Whh,
    const float* __restrict__ bih, const float* __restrict__ bhh)
{
    extern __shared__ unsigned char smc[];
    const int tid=threadIdx.x, w=tid>>5, lane=tid&31;
    const int mw=w&3, uw=w>>2;
    const int r0w=mw*16, u0w=uw*32;
    const int cta=blockIdx.x;
    const uu smb=s2u(smc);
    float* bias=(float*)(smc+SM_BIAS);
    float* xw=(float*)(smc+SM_XW);
    float* sw=(float*)(smc+SM_SIW);

    const uu arow=(uu)((r0w+(lane&15))*144 + ((lane>>4)&1)*16);   // A: X/H tiles
    const uu brow=(uu)((lane&7)*144 + ((lane>>3)&1)*16);          // B: W tiles

    // stage x windows + siW/sib (once per CTA)
    for(int i=tid;i<2048;i+=256){
        int r=i>>5, tt=i&31;
        int g=cta*MROWS+r;
        float v=0.f;
        if(g<BS_TOT){ int b=g/NS, s=g-b*NS; v=x[b*T_LEN+s*16+tt]; }
        xw[i]=v;
    }
    if(tid<64){ sw[tid]=siW[tid]; sw[64+tid]=sib[tid]; }
    __syncthreads();

    const int gr=tid>>2, gc=tid&3;   // layer-0 generator assignment

    for(int l=0;l<4;++l){
        const uint4* inb = d_lay[l&1] + (size_t)cta*32*TILE_U4;
        uu* outb = (uu*)(d_lay[(l+1)&1] + (size_t)cta*32*TILE_U4);

        // stage weights transposed [n][k] fp16
        for(int i=tid;i<12288;i+=256){
            int k=i/192, n=i-k*192;
            uu off=(uu)(n*144+k*2);
            *(__half*)(smc+SM_WI+off)=__float2half_rn(Wih[l*12288+i]);
            *(__half*)(smc+SM_WH+off)=__float2half_rn(Whh[l*12288+i]);
        }
        if(tid<128)      bias[tid]=bih[l*192+tid]+bhh[l*192+tid];   // r,z combined
        else if(tid<192) bias[tid]=bih[l*192+tid];                  // xn (cols 128..191)
        else             bias[tid]=bhh[l*192+tid-64];               // hn (cols 128..191)

        // stage X(0)
        if(l==0){
            float xv=xw[gr*32+0];
            #pragma unroll
            for(int i=0;i<8;++i){
                int k=gc*16+i*2;
                float v0=fmaxf(xv*sw[k]+sw[64+k],0.f);
                float v1=fmaxf(xv*sw[k+1]+sw[64+k+1],0.f);
                *(uu*)(smc+SM_X+gr*144+k*2)=pack2h(v0,v1);
            }
        } else {
            uint4* xs=(uint4*)(smc+SM_X);
            for(int i=tid;i<TILE_U4;i+=256) xs[i]=inb[i];
        }
        __syncthreads();

        float hp[4][4];
        #pragma unroll
        for(int c=0;c<4;++c){ hp[c][0]=0.f;hp[c][1]=0.f;hp[c][2]=0.f;hp[c][3]=0.f; }

        #pragma unroll 1
        for(int t=0;t<32;++t){
            float Ar[4][4],Az[4][4],Ax[4][4],Ah[4][4];
            #pragma unroll
            for(int c=0;c<4;++c)
                #pragma unroll
                for(int e=0;e<4;++e){ Ar[c][e]=0.f;Az[c][e]=0.f;Ax[c][e]=0.f;Ah[c][e]=0.f; }

            #pragma unroll
            for(int kt=0;kt<4;++kt){
                uu ax[4],ah[4];
                uu bb[48];     // distinct regs: [ct][mat(6)][2]
                ldsm4(ax, smb+SM_X+arow+kt*32);
                if(t) ldsm4(ah, smb+SM_H+arow+kt*32);
                #pragma unroll
                for(int ct=0;ct<4;++ct){
                    const uu nR=(uu)((u0w+ct*8)*144);
                    ldsm2(&bb[ct*12+0], smb+SM_WI+nR+brow+kt*32);            // Wi_r
                    ldsm2(&bb[ct*12+2], smb+SM_WI+nR+9216u+brow+kt*32);      // Wi_z
                    ldsm2(&bb[ct*12+4], smb+SM_WI+nR+18432u+brow+kt*32);     // Wi_n
                    if(t){
                        ldsm2(&bb[ct*12+6],  smb+SM_WH+nR+brow+kt*32);       // Wh_r
                        ldsm2(&bb[ct*12+8],  smb+SM_WH+nR+9216u+brow+kt*32); // Wh_z
                        ldsm2(&bb[ct*12+10], smb+SM_WH+nR+18432u+brow+kt*32);// Wh_n
                    }
                }
                #pragma unroll
                for(int ct=0;ct<4;++ct){
                    mma16816(Ar[ct],ax,&bb[ct*12+0]);
                    mma16816(Az[ct],ax,&bb[ct*12+2]);
                    mma16816(Ax[ct],ax,&bb[ct*12+4]);
                    if(t){
                        mma16816(Ar[ct],ah,&bb[ct*12+6]);
                        mma16816(Az[ct],ah,&bb[ct*12+8]);
                        mma16816(Ah[ct],ah,&bb[ct*12+10]);
                    }
                }
            }

            // prefetch / generate next X tile
            uint4 pf[3];
            uu gh[8];
            if(t<31){
                if(l==0){
                    float xv=xw[gr*32+t+1];
                    #pragma unroll
                    for(int i=0;i<8;++i){
                        int k=gc*16+i*2;
                        float v0=fmaxf(xv*sw[k]+sw[64+k],0.f);
                        float v1=fmaxf(xv*sw[k+1]+sw[64+k+1],0.f);
                        gh[i]=pack2h(v0,v1);
                    }
                } else {
                    const uint4* nx=inb+(size_t)(t+1)*TILE_U4;
                    #pragma unroll
                    for(int j=0;j<3;++j){ int idx=tid+j*256; if(idx<TILE_U4) pf[j]=nx[idx]; }
                }
            }

            // gates via MUFU.TANH: 3 MUFU/element (was 3 exp + 2 rcp)
            float hv[4][4];
            #pragma unroll
            for(int ct=0;ct<4;++ct){
                const int ue=u0w+ct*8+(lane&3)*2;
                #pragma unroll
                for(int e=0;e<4;++e){
                    const int u=ue+(e&1);
                    float ar=Ar[ct][e]+bias[u];
                    float az=Az[ct][e]+bias[64+u];
                    float ax2=Ax[ct][e]+bias[128+u];
                    float ah2=Ah[ct][e]+bias[192+u];
                    float r=0.5f+0.5f*tanh_ap(0.5f*ar);
                    float z=0.5f+0.5f*tanh_ap(0.5f*az);
                    float n=tanh_ap(ax2+r*ah2);
                    float hn=z*(hp[ct][e]-n)+n;
                    hp[ct][e]=hn; hv[ct][e]=hn;
                }
            }

            __syncthreads();   // S1: all smem reads of step t complete

            const bool wout=(l<3);
            uu* oti=outb+(size_t)t*2304;
            #pragma unroll
            for(int ct=0;ct<4;++ct){
                const int ue=u0w+ct*8+(lane&3)*2;
                const int rA=r0w+(lane>>2);
                *(uu*)(smc+SM_H+rA*144+ue*2)    =pack2h(hv[ct][0],hv[ct][1]);
                *(uu*)(smc+SM_H+(rA+8)*144+ue*2)=pack2h(hv[ct][2],hv[ct][3]);
                if(wout){
                    oti[rA*36+(ue>>1)]    =pack2h(fmaxf(hv[ct][0],0.f),fmaxf(hv[ct][1],0.f));
                    oti[(rA+8)*36+(ue>>1)]=pack2h(fmaxf(hv[ct][2],0.f),fmaxf(hv[ct][3],0.f));
                }
            }
            if(t<31){
                if(l==0){
                    #pragma unroll
                    for(int i=0;i<8;++i){
                        int k=gc*16+i*2;
                        *(uu*)(smc+SM_X+gr*144+k*2)=gh[i];
                    }
                } else {
                    uint4* xs=(uint4*)(smc+SM_X);
                    #pragma unroll
                    for(int j=0;j<3;++j){ int idx=tid+j*256; if(idx<TILE_U4) xs[idx]=pf[j]; }
                }
            }
            __syncthreads();   // S2: writes visible for step t+1
        }
    }

    // ---- fused head: eps = relu(h31) @ W2 + b2 -> d_A, d_G -------------------
    float* w2s=(float*)(smc+SM_WI);             // 16 KB at 18432..34816
    float* b2s=(float*)(smc+SM_WI+16384);       // 256 B at 34816..35072
    float* hr =(float*)(smc+SM_WH);             // 64x65 f32 at 46080..62720
    for(int i=tid;i<4096;i+=256) w2s[i]=d_W2[i];
    if(tid<64) b2s[tid]=d_b2[tid];
    for(int i=tid;i<4096;i+=256){
        int m=i>>6, k=i&63;
        float v=__half2float(*(const __half*)(smc+SM_H+m*144+k*2));
        hr[m*65+k]=fmaxf(v,0.f);
    }
    __syncthreads();
    for(int i=tid;i<4096;i+=256){
        int m=i>>6, u=i&63;
        float a=b2s[u];
        #pragma unroll 8
        for(int k=0;k<64;++k) a+=hr[m*65+k]*w2s[k*64+u];
        int g=cta*MROWS+m;
        if(g<BS_TOT){
            if(u<HFAST) d_A[g*HFAST+u]=sigm(a);
            else        d_G[g*HFAST+u-HFAST]=a;
        }
    }
}

// ---- fuse: W2 = soW @ s2sW, b2 = sob @ s2sW + s2sb ----------------------------
__global__ void fuse_kernel(const float* __restrict__ soW, const float* __restrict__ sob,
                            const float* __restrict__ s2sW, const float* __restrict__ s2sb)
{
    int tid=threadIdx.x;
    for(int i=tid;i<4096;i+=256){
        int k=i>>6, v=i&63;
        float a=0.f;
        for(int u=0;u<64;++u) a+=soW[k*64+u]*s2sW[u*64+v];
        d_W2[i]=a;
    }
    if(tid<64){
        float a=s2sb[tid];
        for(int u=0;u<64;++u) a+=sob[u]*s2sW[u*64+tid];
        d_b2[tid]=a;
    }
}

// ---- fast path + overlap-add (verified) ----------------------------------------
__global__ void __launch_bounds__(256) fast_kernel(
    const float* __restrict__ x, const float* __restrict__ finW,
    const float* __restrict__ finb, const float* __restrict__ foutW,
    const float* __restrict__ foutb)
{
    int w=(blockIdx.x*blockDim.x+threadIdx.x)>>5;
    int h=threadIdx.x&31;
    if(w>=BS_TOT) return;
    int b=w/NF, f=w-b*NF;
    float A=d_A[w*HFAST+h], G=d_G[w*HFAST+h];
    float fw=__ldg(&finW[h]), fb=__ldg(&finb[h]);
    float fo=__ldg(&foutW[h]), fob=__ldg(&foutb[0]);
    const float* xp=x+b*T_LEN+f*16;
    float hsv=0.f;
    #pragma unroll
    for(int t=0;t<32;++t){
        float e=(xp[t]*fw+fb)*G;
        hsv=A*hsv+e;
        float y=hsv*fo;
        #pragma unroll
        for(int mm=16;mm;mm>>=1) y+=__shfl_xor_sync(0xffffffffu,y,mm);
        if(h==t) d_S[w*32+t]=y+fob;
    }
}
__global__ void __launch_bounds__(256) oadd_kernel(float* __restrict__ out)
{
    int idx=blockIdx.x*blockDim.x+threadIdx.x;
    if(idx>=B_SZ*T_LEN) return;
    int b=idx/T_LEN, i=idx-b*T_LEN;
    int f1=i>>4, j=i&15;
    float v=0.f;
    if(f1<NF) v+=d_S[(b*NF+f1)*32+j];
    if(f1>=1) v+=d_S[(b*NF+f1-1)*32+j+16];
    out[idx]=v;
}

extern "C" void kernel_launch(void* const* d_in, const int* in_sizes, int n_in,
                              void* d_out, int out_size)
{
    const float* x    =(const float*)d_in[0];
    const float* siW  =(const float*)d_in[1];
    const float* sib  =(const float*)d_in[2];
    const float* Wih  =(const float*)d_in[3];
    const float* Whh  =(const float*)d_in[4];
    const float* bih  =(const float*)d_in[5];
    const float* bhh  =(const float*)d_in[6];
    const float* soW  =(const float*)d_in[7];
    const float* sob  =(const float*)d_in[8];
    const float* s2sW =(const float*)d_in[9];
    const float* s2sb =(const float*)d_in[10];
    const float* finW =(const float*)d_in[11];
    const float* finb =(const float*)d_in[12];
    const float* foW  =(const float*)d_in[13];
    const float* fob  =(const float*)d_in[14];
    float* out=(float*)d_out;

    cudaFuncSetAttribute(slow_kernel, cudaFuncAttributeMaxDynamicSharedMemorySize, SMEM_SZ);
    fuse_kernel<<<1,256>>>(soW,sob,s2sW,s2sb);
    slow_kernel<<<NCTA,256,SMEM_SZ>>>(x,siW,sib,Wih,Whh,bih,bhh);
    fast_kernel<<<(BS_TOT*32+255)/256,256>>>(x,finW,finb,foW,fob);
    oadd_kernel<<<(B_SZ*T_LEN+255)/256,256>>>(out);
}

// round 17
// speedup vs baseline: 2.6755x; 1.0491x over previous
#include <cuda_runtime.h>
#include <cuda_fp16.h>
#include <math.h>
#include <stdint.h>

#define T_LEN 64000
#define B_SZ  2
#define NS    3999
#define NF    3999
#define BS_TOT (B_SZ*NS)
#define HFAST 32
#define NCTA  252
#define MROWS 32
#define TILE_U4 288             // uint4 per layer-IO tile (fp16 [32][72])

// smem byte offsets
#define SM_X   0                // X [32][72] fp16
#define SM_H   4608             // H [32][72] fp16
#define SM_WI  9216             // Wih^T [192][72] fp16
#define SM_WH  36864            // Whh^T [192][72] fp16
#define SM_BIAS 64512           // 256 floats
#define SM_XW   65536           // x windows [32][32] f32
#define SM_SIW  69632           // siW[64], sib[64]
#define SMEM_SZ 70144

__device__ uint4 d_lay[2][(size_t)NCTA*32*TILE_U4];
__device__ float d_W2[64*64];
__device__ float d_b2[64];
__device__ float d_A[BS_TOT*HFAST];
__device__ float d_G[BS_TOT*HFAST];
__device__ float d_S[BS_TOT*32];

typedef unsigned uu;

__device__ __forceinline__ uu s2u(const void* p){
    uu a; asm("{.reg .u64 t; cvta.to.shared.u64 t,%1; cvt.u32.u64 %0,t;}":"=r"(a):"l"(p)); return a;
}
__device__ __forceinline__ void ldsm4(uu* r, uu a){
    asm volatile("ldmatrix.sync.aligned.m8n8.x4.shared.b16 {%0,%1,%2,%3},[%4];"
        :"=r"(r[0]),"=r"(r[1]),"=r"(r[2]),"=r"(r[3]):"r"(a));
}
__device__ __forceinline__ void ldsm2(uu* r, uu a){
    asm volatile("ldmatrix.sync.aligned.m8n8.x2.shared.b16 {%0,%1},[%2];"
        :"=r"(r[0]),"=r"(r[1]):"r"(a));
}
__device__ __forceinline__ void mma16816(float* d, const uu* a, const uu* b){
    asm volatile("mma.sync.aligned.m16n8k16.row.col.f32.f16.f16.f32 "
        "{%0,%1,%2,%3},{%4,%5,%6,%7},{%8,%9},{%0,%1,%2,%3};"
        :"+f"(d[0]),"+f"(d[1]),"+f"(d[2]),"+f"(d[3])
        :"r"(a[0]),"r"(a[1]),"r"(a[2]),"r"(a[3]),"r"(b[0]),"r"(b[1]));
}
__device__ __forceinline__ float tanh_ap(float x){
    float r; asm("tanh.approx.f32 %0,%1;":"=f"(r):"f"(x)); return r;
}
__device__ __forceinline__ uu pack2h(float a, float b){
    __half2 h=__floats2half2_rn(a,b); return *(uu*)&h;
}
__device__ __forceinline__ float sigm(float x){ return 0.5f+0.5f*tanh_ap(0.5f*x); }

// ---- slow: mma.sync fp16 GRU, 32-row tiles, 2 CTAs/SM -------------------------
__global__ void __launch_bounds__(256,2) slow_kernel(
    const float* __restrict__ x,
    const float* __restrict__ siW, const float* __restrict__ sib,
    const float* __restrict__ Wih, const float* __restrict__ Whh,
    const float* __restrict__ bih, const float* __restrict__ bhh)
{
    extern __shared__ unsigned char smc[];
    const int tid=threadIdx.x, w=tid>>5, lane=tid&31;
    const int mw=w&1, uw=w>>1;          // 2 M-groups x 4 unit-groups
    const int r0w=mw*16, u0w=uw*16;
    const int cta=blockIdx.x;
    const uu smb=s2u(smc);
    float* bias=(float*)(smc+SM_BIAS);
    float* xw=(float*)(smc+SM_XW);
    float* sw=(float*)(smc+SM_SIW);

    const uu arow=(uu)((r0w+(lane&15))*144 + ((lane>>4)&1)*16);   // A: X/H tiles
    const uu brow=(uu)((lane&7)*144 + ((lane>>3)&1)*16);          // B: W tiles

    // stage x windows + siW/sib (once per CTA)
    for(int i=tid;i<1024;i+=256){
        int r=i>>5, tt=i&31;
        int g=cta*MROWS+r;
        float v=0.f;
        if(g<BS_TOT){ int b=g/NS, s=g-b*NS; v=x[b*T_LEN+s*16+tt]; }
        xw[i]=v;
    }
    if(tid<64){ sw[tid]=siW[tid]; sw[64+tid]=sib[tid]; }
    __syncthreads();

    const int gr=tid>>3, gc=tid&7;   // layer-0 generator: 8 threads/row, 8 k's each

    for(int l=0;l<4;++l){
        const uint4* inb = d_lay[l&1] + (size_t)cta*32*TILE_U4;
        uu* outb = (uu*)(d_lay[(l+1)&1] + (size_t)cta*32*TILE_U4);

        // stage weights transposed [n][k] fp16
        for(int i=tid;i<12288;i+=256){
            int k=i/192, n=i-k*192;
            uu off=(uu)(n*144+k*2);
            *(__half*)(smc+SM_WI+off)=__float2half_rn(Wih[l*12288+i]);
            *(__half*)(smc+SM_WH+off)=__float2half_rn(Whh[l*12288+i]);
        }
        if(tid<128)      bias[tid]=bih[l*192+tid]+bhh[l*192+tid];   // r,z combined
        else if(tid<192) bias[tid]=bih[l*192+tid];                  // xn (cols 128..191)
        else             bias[tid]=bhh[l*192+tid-64];               // hn (cols 128..191)

        // stage X(0)
        if(l==0){
            float xv=xw[gr*32+0];
            #pragma unroll
            for(int i=0;i<4;++i){
                int k=gc*8+i*2;
                float v0=fmaxf(xv*sw[k]+sw[64+k],0.f);
                float v1=fmaxf(xv*sw[k+1]+sw[64+k+1],0.f);
                *(uu*)(smc+SM_X+gr*144+k*2)=pack2h(v0,v1);
            }
        } else {
            uint4* xs=(uint4*)(smc+SM_X);
            for(int i=tid;i<TILE_U4;i+=256) xs[i]=inb[i];
        }
        __syncthreads();

        float hp[2][4];
        #pragma unroll
        for(int c=0;c<2;++c){ hp[c][0]=0.f;hp[c][1]=0.f;hp[c][2]=0.f;hp[c][3]=0.f; }

        #pragma unroll 1
        for(int t=0;t<32;++t){
            float Ar[2][4],Az[2][4],Ax[2][4],Ah[2][4];
            #pragma unroll
            for(int c=0;c<2;++c)
                #pragma unroll
                for(int e=0;e<4;++e){ Ar[c][e]=0.f;Az[c][e]=0.f;Ax[c][e]=0.f;Ah[c][e]=0.f; }

            #pragma unroll
            for(int kt=0;kt<4;++kt){
                uu ax[4],ah[4];
                uu bb[24];     // distinct regs: [ct][mat(6)][2]
                ldsm4(ax, smb+SM_X+arow+kt*32);
                if(t) ldsm4(ah, smb+SM_H+arow+kt*32);
                #pragma unroll
                for(int ct=0;ct<2;++ct){
                    const uu nR=(uu)((u0w+ct*8)*144);
                    ldsm2(&bb[ct*12+0], smb+SM_WI+nR+brow+kt*32);            // Wi_r
                    ldsm2(&bb[ct*12+2], smb+SM_WI+nR+9216u+brow+kt*32);      // Wi_z
                    ldsm2(&bb[ct*12+4], smb+SM_WI+nR+18432u+brow+kt*32);     // Wi_n
                    if(t){
                        ldsm2(&bb[ct*12+6],  smb+SM_WH+nR+brow+kt*32);       // Wh_r
                        ldsm2(&bb[ct*12+8],  smb+SM_WH+nR+9216u+brow+kt*32); // Wh_z
                        ldsm2(&bb[ct*12+10], smb+SM_WH+nR+18432u+brow+kt*32);// Wh_n
                    }
                }
                #pragma unroll
                for(int ct=0;ct<2;++ct){
                    mma16816(Ar[ct],ax,&bb[ct*12+0]);
                    mma16816(Az[ct],ax,&bb[ct*12+2]);
                    mma16816(Ax[ct],ax,&bb[ct*12+4]);
                    if(t){
                        mma16816(Ar[ct],ah,&bb[ct*12+6]);
                        mma16816(Az[ct],ah,&bb[ct*12+8]);
                        mma16816(Ah[ct],ah,&bb[ct*12+10]);
                    }
                }
            }

            // prefetch / generate next X tile
            uint4 pf[2];
            uu gh[4];
            if(t<31){
                if(l==0){
                    float xv=xw[gr*32+t+1];
                    #pragma unroll
                    for(int i=0;i<4;++i){
                        int k=gc*8+i*2;
                        float v0=fmaxf(xv*sw[k]+sw[64+k],0.f);
                        float v1=fmaxf(xv*sw[k+1]+sw[64+k+1],0.f);
                        gh[i]=pack2h(v0,v1);
                    }
                } else {
                    const uint4* nx=inb+(size_t)(t+1)*TILE_U4;
                    #pragma unroll
                    for(int j=0;j<2;++j){ int idx=tid+j*256; if(idx<TILE_U4) pf[j]=nx[idx]; }
                }
            }

            // gates via MUFU.TANH
            float hv[2][4];
            #pragma unroll
            for(int ct=0;ct<2;++ct){
                const int ue=u0w+ct*8+(lane&3)*2;
                #pragma unroll
                for(int e=0;e<4;++e){
                    const int u=ue+(e&1);
                    float ar=Ar[ct][e]+bias[u];
                    float az=Az[ct][e]+bias[64+u];
                    float ax2=Ax[ct][e]+bias[128+u];
                    float ah2=Ah[ct][e]+bias[192+u];
                    float r=0.5f+0.5f*tanh_ap(0.5f*ar);
                    float z=0.5f+0.5f*tanh_ap(0.5f*az);
                    float n=tanh_ap(ax2+r*ah2);
                    float hn=z*(hp[ct][e]-n)+n;
                    hp[ct][e]=hn; hv[ct][e]=hn;
                }
            }

            __syncthreads();   // S1: all smem reads of step t complete

            const bool wout=(l<3);
            uu* oti=outb+(size_t)t*1152;
            #pragma unroll
            for(int ct=0;ct<2;++ct){
                const int ue=u0w+ct*8+(lane&3)*2;
                const int rA=r0w+(lane>>2);
                *(uu*)(smc+SM_H+rA*144+ue*2)    =pack2h(hv[ct][0],hv[ct][1]);
                *(uu*)(smc+SM_H+(rA+8)*144+ue*2)=pack2h(hv[ct][2],hv[ct][3]);
                if(wout){
                    oti[rA*36+(ue>>1)]    =pack2h(fmaxf(hv[ct][0],0.f),fmaxf(hv[ct][1],0.f));
                    oti[(rA+8)*36+(ue>>1)]=pack2h(fmaxf(hv[ct][2],0.f),fmaxf(hv[ct][3],0.f));
                }
            }
            if(t<31){
                if(l==0){
                    #pragma unroll
                    for(int i=0;i<4;++i){
                        int k=gc*8+i*2;
                        *(uu*)(smc+SM_X+gr*144+k*2)=gh[i];
                    }
                } else {
                    uint4* xs=(uint4*)(smc+SM_X);
                    #pragma unroll
                    for(int j=0;j<2;++j){ int idx=tid+j*256; if(idx<TILE_U4) xs[idx]=pf[j]; }
                }
            }
            __syncthreads();   // S2: writes visible for step t+1
        }
    }

    // ---- fused head: eps = relu(h31) @ W2 + b2 -> d_A, d_G -------------------
    float* w2s=(float*)(smc+SM_WI);             // 16 KB at 9216..25600
    float* b2s=(float*)(smc+SM_WI+16384);       // 256 B
    float* hr =(float*)(smc+SM_WH);             // 32x65 f32 at 36864..45184
    for(int i=tid;i<4096;i+=256) w2s[i]=d_W2[i];
    if(tid<64) b2s[tid]=d_b2[tid];
    for(int i=tid;i<2048;i+=256){
        int m=i>>6, k=i&63;
        float v=__half2float(*(const __half*)(smc+SM_H+m*144+k*2));
        hr[m*65+k]=fmaxf(v,0.f);
    }
    __syncthreads();
    for(int i=tid;i<2048;i+=256){
        int m=i>>6, u=i&63;
        float a=b2s[u];
        #pragma unroll 8
        for(int k=0;k<64;++k) a+=hr[m*65+k]*w2s[k*64+u];
        int g=cta*MROWS+m;
        if(g<BS_TOT){
            if(u<HFAST) d_A[g*HFAST+u]=sigm(a);
            else        d_G[g*HFAST+u-HFAST]=a;
        }
    }
}

// ---- fuse: W2 = soW @ s2sW, b2 = sob @ s2sW + s2sb ----------------------------
__global__ void fuse_kernel(const float* __restrict__ soW, const float* __restrict__ sob,
                            const float* __restrict__ s2sW, const float* __restrict__ s2sb)
{
    int tid=threadIdx.x;
    for(int i=tid;i<4096;i+=256){
        int k=i>>6, v=i&63;
        float a=0.f;
        for(int u=0;u<64;++u) a+=soW[k*64+u]*s2sW[u*64+v];
        d_W2[i]=a;
    }
    if(tid<64){
        float a=s2sb[tid];
        for(int u=0;u<64;++u) a+=sob[u]*s2sW[u*64+tid];
        d_b2[tid]=a;
    }
}

// ---- fast path + overlap-add (verified) ----------------------------------------
__global__ void __launch_bounds__(256) fast_kernel(
    const float* __restrict__ x, const float* __restrict__ finW,
    const float* __restrict__ finb, const float* __restrict__ foutW,
    const float* __restrict__ foutb)
{
    int w=(blockIdx.x*blockDim.x+threadIdx.x)>>5;
    int h=threadIdx.x&31;
    if(w>=BS_TOT) return;
    int b=w/NF, f=w-b*NF;
    float A=d_A[w*HFAST+h], G=d_G[w*HFAST+h];
    float fw=__ldg(&finW[h]), fb=__ldg(&finb[h]);
    float fo=__ldg(&foutW[h]), fob=__ldg(&foutb[0]);
    const float* xp=x+b*T_LEN+f*16;
    float hsv=0.f;
    #pragma unroll
    for(int t=0;t<32;++t){
        float e=(xp[t]*fw+fb)*G;
        hsv=A*hsv+e;
        float y=hsv*fo;
        #pragma unroll
        for(int mm=16;mm;mm>>=1) y+=__shfl_xor_sync(0xffffffffu,y,mm);
        if(h==t) d_S[w*32+t]=y+fob;
    }
}
__global__ void __launch_bounds__(256) oadd_kernel(float* __restrict__ out)
{
    int idx=blockIdx.x*blockDim.x+threadIdx.x;
    if(idx>=B_SZ*T_LEN) return;
    int b=idx/T_LEN, i=idx-b*T_LEN;
    int f1=i>>4, j=i&15;
    float v=0.f;
    if(f1<NF) v+=d_S[(b*NF+f1)*32+j];
    if(f1>=1) v+=d_S[(b*NF+f1-1)*32+j+16];
    out[idx]=v;
}

extern "C" void kernel_launch(void* const* d_in, const int* in_sizes, int n_in,
                              void* d_out, int out_size)
{
    const float* x    =(const float*)d_in[0];
    const float* siW  =(const float*)d_in[1];
    const float* sib  =(const float*)d_in[2];
    const float* Wih  =(const float*)d_in[3];
    const float* Whh  =(const float*)d_in[4];
    const float* bih  =(const float*)d_in[5];
    const float* bhh  =(const float*)d_in[6];
    const float* soW  =(const float*)d_in[7];
    const float* sob  =(const float*)d_in[8];
    const float* s2sW =(const float*)d_in[9];
    const float* s2sb =(const float*)d_in[10];
    const float* finW =(const float*)d_in[11];
    const float* finb =(const float*)d_in[12];
    const float* foW  =(const float*)d_in[13];
    const float* fob  =(const float*)d_in[14];
    float* out=(float*)d_out;

    cudaFuncSetAttribute(slow_kernel, cudaFuncAttributeMaxDynamicSharedMemorySize, SMEM_SZ);
    fuse_kernel<<<1,256>>>(soW,sob,s2sW,s2sb);
    slow_kernel<<<NCTA,256,SMEM_SZ>>>(x,siW,sib,Wih,Whh,bih,bhh);
    fast_kernel<<<(BS_TOT*32+255)/256,256>>>(x,finW,finb,foW,fob);
    oadd_kernel<<<(B_SZ*T_LEN+255)/256,256>>>(out);
}